// round 1
// baseline (speedup 1.0000x reference)
#include <cuda_runtime.h>
#include <math.h>
#include <float.h>

#define N_TOK 1024
#define CT    768
#define CS    384
#define CP    16
#define NH    16
#define DH    48
#define NB    4
#define NLOC  8
#define NKNN  32
#define KTOT  40

static __device__ float g_sn   [N_TOK*CS];
static __device__ float g_normA[N_TOK*CT];
static __device__ float g_an   [N_TOK*CT];
static __device__ float g_q    [N_TOK*CT];
static __device__ float g_kb   [N_TOK*CT];
static __device__ float g_vb   [N_TOK*CT];
static __device__ float g_gpre [N_TOK*CT];
static __device__ float g_otmp [N_TOK*CT];
static __device__ float g_ptmp [N_TOK*CT];
static __device__ float g_hb   [N_TOK*2*CT];
static __device__ float g_zn   [N_TOK*KTOT*CP];
static __device__ int   g_idx  [N_TOK*KTOT];
static __device__ float g_wbf  [CP*NH];
static __device__ float g_b0   [NH];

__device__ __forceinline__ float sigmoidf_(float x) { return 1.0f / (1.0f + expf(-x)); }

// ---------------------------------------------------------------------------
// kNN indices: for each token, 8 clamped local + top-32 nearest by squared
// distance (ties -> lowest index, matching jax.lax.top_k on -d2).
// ---------------------------------------------------------------------------
__global__ void idx_kernel(const float* __restrict__ X, int* __restrict__ idx) {
    int n = blockIdx.x;
    int tid = threadIdx.x;
    __shared__ float sd[N_TOK];
    __shared__ float rv[256];
    __shared__ int   ri[256];

    float x0 = X[n*3+0], x1 = X[n*3+1], x2 = X[n*3+2];
    for (int j = tid; j < N_TOK; j += 256) {
        float d0 = x0 - X[j*3+0];
        float d1 = x1 - X[j*3+1];
        float d2 = x2 - X[j*3+2];
        sd[j] = d0*d0 + d1*d1 + d2*d2;
    }
    if (tid < NLOC) {
        int v = n - NLOC/2 + tid;
        v = min(max(v, 0), N_TOK-1);
        idx[n*KTOT + tid] = v;
    }
    __syncthreads();

    for (int s = 0; s < NKNN; s++) {
        float best = FLT_MAX; int bi = N_TOK;
        for (int j = tid; j < N_TOK; j += 256) {
            float v = sd[j];
            if (v < best || (v == best && j < bi)) { best = v; bi = j; }
        }
        rv[tid] = best; ri[tid] = bi;
        __syncthreads();
        for (int off = 128; off > 0; off >>= 1) {
            if (tid < off) {
                if (rv[tid+off] < rv[tid] || (rv[tid+off] == rv[tid] && ri[tid+off] < ri[tid])) {
                    rv[tid] = rv[tid+off]; ri[tid] = ri[tid+off];
                }
            }
            __syncthreads();
        }
        if (tid == 0) {
            idx[n*KTOT + NLOC + s] = ri[0];
            sd[ri[0]] = FLT_MAX;
        }
        __syncthreads();
    }
}

// ---------------------------------------------------------------------------
// Gather pair reps + LayerNorm (no affine; affine folded into Wb later).
// ---------------------------------------------------------------------------
__global__ void zn_kernel(const float* __restrict__ Z, const int* __restrict__ idx,
                          float* __restrict__ zn) {
    int e = blockIdx.x * blockDim.x + threadIdx.x;  // over N_TOK*KTOT rows
    if (e >= N_TOK*KTOT) return;
    int n = e / KTOT;
    int j = idx[e];
    const float* z = Z + ((size_t)n * N_TOK + j) * CP;
    float m = 0.f;
#pragma unroll
    for (int c = 0; c < CP; c++) m += z[c];
    m *= (1.0f/CP);
    float v = 0.f;
#pragma unroll
    for (int c = 0; c < CP; c++) { float d = z[c]-m; v += d*d; }
    v *= (1.0f/CP);
    float r = rsqrtf(v + 1e-5f);
#pragma unroll
    for (int c = 0; c < CP; c++) zn[(size_t)e*CP + c] = (z[c]-m)*r;
}

// ---------------------------------------------------------------------------
// Row LayerNorm (optional gamma), width W (384 or 768).
// ---------------------------------------------------------------------------
__global__ void ln_kernel(const float* __restrict__ X, const float* __restrict__ gamma,
                          float* __restrict__ Y, int W) {
    int n = blockIdx.x;
    int tid = threadIdx.x;
    const float* x = X + (size_t)n * W;
    __shared__ float red[256];

    float s = 0.f;
    for (int c = tid; c < W; c += 256) s += x[c];
    red[tid] = s; __syncthreads();
    for (int o = 128; o > 0; o >>= 1) { if (tid < o) red[tid] += red[tid+o]; __syncthreads(); }
    float m = red[0] / W;
    __syncthreads();

    float v = 0.f;
    for (int c = tid; c < W; c += 256) { float d = x[c]-m; v += d*d; }
    red[tid] = v; __syncthreads();
    for (int o = 128; o > 0; o >>= 1) { if (tid < o) red[tid] += red[tid+o]; __syncthreads(); }
    float var = red[0] / W;
    float r = rsqrtf(var + 1e-5f);

    for (int c = tid; c < W; c += 256) {
        float g = gamma ? gamma[c] : 1.0f;
        Y[(size_t)n*W + c] = (x[c]-m)*r*g;
    }
}

// ---------------------------------------------------------------------------
// Fold pair LN affine into Wb:  wbf[c][h] = g[c]*Wb[c][h],  b0[h] = sum_c b[c]*Wb[c][h]
// ---------------------------------------------------------------------------
__global__ void fold_wb_kernel(const float* __restrict__ g, const float* __restrict__ b,
                               const float* __restrict__ Wb,
                               float* __restrict__ wbf, float* __restrict__ b0) {
    int t = threadIdx.x;
    if (t < CP*NH) {
        int c = t / NH;
        wbf[t] = g[c] * Wb[t];
    }
    if (t < NH) {
        float s = 0.f;
#pragma unroll
        for (int c = 0; c < CP; c++) s += b[c] * Wb[c*NH + t];
        b0[t] = s;
    }
}

// ---------------------------------------------------------------------------
// Tiled fp32 GEMM, 64x64x16 tiles, 4x4 per thread, with fused epilogues.
// A[M,K] row-major, B[K,N] row-major.
// MODE 0: C = acc1 + bias[c]            (bias nullable)
// MODE 1: C = sigmoid(acc1+bias[c]) * extra[m*N+c] + acc2      (adaLN)
// MODE 2: C += sigmoid(acc1+bias[c]) * extra[m*N+c]            (skip gate-add)
// MODE 3: C = silu(acc1) * acc2                                 (SwiGLU)
// ---------------------------------------------------------------------------
#define BM 64
#define BN 64
#define BK 16

template<int MODE>
__global__ void gemm_kernel(const float* __restrict__ A, const float* __restrict__ B1,
                            const float* __restrict__ B2, const float* __restrict__ bias,
                            const float* __restrict__ extra, float* __restrict__ C,
                            int M, int N, int K) {
    constexpr bool DUAL = (MODE == 1 || MODE == 3);
    __shared__ float As[BK][BM];
    __shared__ float Bs[BK][BN];
    __shared__ float Bs2[DUAL ? BK : 1][BN];

    int tid = threadIdx.x;
    int tx = tid & 15;
    int ty = tid >> 4;
    int row0 = blockIdx.y * BM;
    int col0 = blockIdx.x * BN;

    float acc[4][4] = {};
    float acc2[4][4] = {};

    for (int k0 = 0; k0 < K; k0 += BK) {
        // load A tile (BM x BK) -> As[kk][m]
        for (int l = tid; l < BM*BK; l += 256) {
            int m = l >> 4, kk = l & 15;
            As[kk][m] = A[(size_t)(row0 + m)*K + k0 + kk];
        }
        // load B tiles (BK x BN) -> Bs[kk][n]
        for (int l = tid; l < BK*BN; l += 256) {
            int kk = l >> 6, nn = l & 63;
            Bs[kk][nn] = B1[(size_t)(k0 + kk)*N + col0 + nn];
            if (DUAL) Bs2[kk][nn] = B2[(size_t)(k0 + kk)*N + col0 + nn];
        }
        __syncthreads();

#pragma unroll
        for (int kk = 0; kk < BK; kk++) {
            float a[4], b[4], b2[4];
#pragma unroll
            for (int i = 0; i < 4; i++) a[i] = As[kk][ty*4 + i];
#pragma unroll
            for (int j = 0; j < 4; j++) b[j] = Bs[kk][tx*4 + j];
            if (DUAL) {
#pragma unroll
                for (int j = 0; j < 4; j++) b2[j] = Bs2[kk][tx*4 + j];
            }
#pragma unroll
            for (int i = 0; i < 4; i++)
#pragma unroll
                for (int j = 0; j < 4; j++) {
                    acc[i][j] += a[i]*b[j];
                    if (DUAL) acc2[i][j] += a[i]*b2[j];
                }
        }
        __syncthreads();
    }

#pragma unroll
    for (int i = 0; i < 4; i++) {
        int m = row0 + ty*4 + i;
#pragma unroll
        for (int j = 0; j < 4; j++) {
            int nn = col0 + tx*4 + j;
            size_t off = (size_t)m*N + nn;
            float v1 = acc[i][j];
            if (MODE == 0) {
                float bv = bias ? bias[nn] : 0.0f;
                C[off] = v1 + bv;
            } else if (MODE == 1) {
                C[off] = sigmoidf_(v1 + bias[nn]) * extra[off] + acc2[i][j];
            } else if (MODE == 2) {
                C[off] += sigmoidf_(v1 + bias[nn]) * extra[off];
            } else { // MODE 3
                float s = v1 * sigmoidf_(v1); // silu
                C[off] = s * acc2[i][j];
            }
        }
    }
}

// ---------------------------------------------------------------------------
// Attention: per-token block. 16 heads x 40 keys, pair bias, softmax,
// weighted V sum, per-channel sigmoid gate (gpre).
// ---------------------------------------------------------------------------
__global__ void attn_kernel(const float* __restrict__ q, const float* __restrict__ kb,
                            const float* __restrict__ vb, const float* __restrict__ gpre,
                            const int* __restrict__ idx, const float* __restrict__ zn,
                            const float* __restrict__ wbf, const float* __restrict__ b0,
                            float* __restrict__ out) {
    const float SCALE = 0.14433756729740643f; // 1/sqrt(48)
    int n = blockIdx.x;
    int tid = threadIdx.x;
    __shared__ float qs[CT];
    __shared__ float zs[KTOT*CP];
    __shared__ int   js[KTOT];
    __shared__ float sc[NH*KTOT];

    for (int c = tid; c < CT; c += 256) qs[c] = q[(size_t)n*CT + c];
    if (tid < KTOT) js[tid] = idx[n*KTOT + tid];
    for (int c = tid; c < KTOT*CP; c += 256) zs[c] = zn[(size_t)n*KTOT*CP + c];
    __syncthreads();

    for (int e = tid; e < NH*KTOT; e += 256) {
        int h = e / KTOT, k = e % KTOT;
        int j = js[k];
        const float* kp = kb + (size_t)j*CT + h*DH;
        const float* qp = qs + h*DH;
        float s = 0.f;
#pragma unroll
        for (int d = 0; d < DH; d++) s += qp[d]*kp[d];
        s *= SCALE;
        float bb = b0[h];
        const float* zp = zs + k*CP;
#pragma unroll
        for (int c = 0; c < CP; c++) bb += zp[c]*wbf[c*NH + h];
        sc[e] = s + bb;
    }
    __syncthreads();

    if (tid < NH) {
        int h = tid;
        float mx = -FLT_MAX;
        for (int k = 0; k < KTOT; k++) mx = fmaxf(mx, sc[h*KTOT + k]);
        float sum = 0.f;
        for (int k = 0; k < KTOT; k++) {
            float ex = expf(sc[h*KTOT + k] - mx);
            sc[h*KTOT + k] = ex; sum += ex;
        }
        float inv = 1.0f / sum;
        for (int k = 0; k < KTOT; k++) sc[h*KTOT + k] *= inv;
    }
    __syncthreads();

    for (int c = tid; c < CT; c += 256) {
        int h = c / DH;
        float acc = 0.f;
#pragma unroll 8
        for (int k = 0; k < KTOT; k++)
            acc += sc[h*KTOT + k] * vb[(size_t)js[k]*CT + c];
        float g = gpre[(size_t)n*CT + c];
        out[(size_t)n*CT + c] = acc * sigmoidf_(g);
    }
}

// ---------------------------------------------------------------------------
extern "C" void kernel_launch(void* const* d_in, const int* in_sizes, int n_in,
                              void* d_out, int out_size) {
    const float* A_I      = (const float*)d_in[0];
    const float* S        = (const float*)d_in[1];
    const float* Z        = (const float*)d_in[2];
    const float* X_L      = (const float*)d_in[3];
    // d_in[4] = f (unused by reference)
    const float* aln1_g   = (const float*)d_in[5];
    const float* aln1_sw  = (const float*)d_in[6];
    const float* aln1_sb  = (const float*)d_in[7];
    const float* aln1_shw = (const float*)d_in[8];
    const float* Wq       = (const float*)d_in[9];
    const float* bq       = (const float*)d_in[10];
    const float* Wk       = (const float*)d_in[11];
    const float* Wv       = (const float*)d_in[12];
    const float* plg      = (const float*)d_in[13];
    const float* plb      = (const float*)d_in[14];
    const float* Wb       = (const float*)d_in[15];
    const float* Wg       = (const float*)d_in[16];
    const float* Wo       = (const float*)d_in[17];
    const float* sgw      = (const float*)d_in[18];
    const float* sgb      = (const float*)d_in[19];
    const float* aln2_g   = (const float*)d_in[20];
    const float* aln2_sw  = (const float*)d_in[21];
    const float* aln2_sb  = (const float*)d_in[22];
    const float* aln2_shw = (const float*)d_in[23];
    const float* tw1      = (const float*)d_in[24];
    const float* tw2      = (const float*)d_in[25];
    const float* tw3      = (const float*)d_in[26];
    const float* tsgw     = (const float*)d_in[27];
    const float* tsgb     = (const float*)d_in[28];

    float* A = (float*)d_out;

    float *sn, *normA, *an, *q, *kb, *vb, *gpre, *otmp, *ptmp, *hb, *zn, *wbf, *b0;
    int* idx;
    cudaGetSymbolAddress((void**)&sn,    g_sn);
    cudaGetSymbolAddress((void**)&normA, g_normA);
    cudaGetSymbolAddress((void**)&an,    g_an);
    cudaGetSymbolAddress((void**)&q,     g_q);
    cudaGetSymbolAddress((void**)&kb,    g_kb);
    cudaGetSymbolAddress((void**)&vb,    g_vb);
    cudaGetSymbolAddress((void**)&gpre,  g_gpre);
    cudaGetSymbolAddress((void**)&otmp,  g_otmp);
    cudaGetSymbolAddress((void**)&ptmp,  g_ptmp);
    cudaGetSymbolAddress((void**)&hb,    g_hb);
    cudaGetSymbolAddress((void**)&zn,    g_zn);
    cudaGetSymbolAddress((void**)&wbf,   g_wbf);
    cudaGetSymbolAddress((void**)&b0,    g_b0);
    cudaGetSymbolAddress((void**)&idx,   g_idx);

    cudaMemcpyAsync(A, A_I, (size_t)N_TOK*CT*sizeof(float), cudaMemcpyDeviceToDevice, 0);

    idx_kernel<<<N_TOK, 256>>>(X_L, idx);
    zn_kernel<<<(N_TOK*KTOT + 255)/256, 256>>>(Z, idx, zn);

    dim3 g768(CT/BN, N_TOK/BM);
    dim3 g1536(2*CT/BN, N_TOK/BM);

    for (int i = 0; i < NB; i++) {
        size_t wo_ct  = (size_t)i*CT*CT;
        size_t wo_cs  = (size_t)i*CS*CT;
        size_t wo_t12 = (size_t)i*CT*2*CT;
        size_t wo_t3  = (size_t)i*2*CT*CT;

        // --- LocalAttentionPairBias ---
        ln_kernel<<<N_TOK, 256>>>(S, aln1_g + i*CS, sn, CS);
        ln_kernel<<<N_TOK, 256>>>(A, nullptr, normA, CT);
        gemm_kernel<1><<<g768, 256>>>(sn, aln1_sw + wo_cs, aln1_shw + wo_cs,
                                      aln1_sb + i*CT, normA, an, N_TOK, CT, CS);
        gemm_kernel<0><<<g768, 256>>>(an, Wq + wo_ct, nullptr, bq + i*CT, nullptr, q,  N_TOK, CT, CT);
        gemm_kernel<0><<<g768, 256>>>(an, Wk + wo_ct, nullptr, nullptr,   nullptr, kb, N_TOK, CT, CT);
        gemm_kernel<0><<<g768, 256>>>(an, Wv + wo_ct, nullptr, nullptr,   nullptr, vb, N_TOK, CT, CT);
        gemm_kernel<0><<<g768, 256>>>(an, Wg + wo_ct, nullptr, nullptr,   nullptr, gpre, N_TOK, CT, CT);
        fold_wb_kernel<<<1, 256>>>(plg + i*CP, plb + i*CP, Wb + i*CP*NH, wbf, b0);
        attn_kernel<<<N_TOK, 256>>>(q, kb, vb, gpre, idx, zn, wbf, b0, otmp);
        gemm_kernel<0><<<g768, 256>>>(otmp, Wo + wo_ct, nullptr, nullptr, nullptr, ptmp, N_TOK, CT, CT);
        gemm_kernel<2><<<g768, 256>>>(S, sgw + wo_cs, nullptr, sgb + i*CT, ptmp, A, N_TOK, CT, CS);

        // --- ConditionedTransitionBlock ---
        ln_kernel<<<N_TOK, 256>>>(S, aln2_g + i*CS, sn, CS);
        ln_kernel<<<N_TOK, 256>>>(A, nullptr, normA, CT);
        gemm_kernel<1><<<g768, 256>>>(sn, aln2_sw + wo_cs, aln2_shw + wo_cs,
                                      aln2_sb + i*CT, normA, an, N_TOK, CT, CS);
        gemm_kernel<3><<<g1536, 256>>>(an, tw1 + wo_t12, tw2 + wo_t12, nullptr, nullptr,
                                       hb, N_TOK, 2*CT, CT);
        gemm_kernel<0><<<g768, 256>>>(hb, tw3 + wo_t3, nullptr, nullptr, nullptr, ptmp, N_TOK, CT, 2*CT);
        gemm_kernel<2><<<g768, 256>>>(S, tsgw + wo_cs, nullptr, tsgb + i*CT, ptmp, A, N_TOK, CT, CS);
    }
}

// round 4
// speedup vs baseline: 2.8942x; 2.8942x over previous
#include <cuda_runtime.h>
#include <math.h>
#include <float.h>

#define N_TOK 1024
#define CT    768
#define CS    384
#define CP    16
#define NH    16
#define DH    48
#define NB    4
#define NLOC  8
#define NKNN  32
#define KTOT  40

static __device__ float g_sn   [N_TOK*CS];
static __device__ float g_normA[N_TOK*CT];
static __device__ float g_an   [N_TOK*CT];
static __device__ float g_q    [N_TOK*CT];
static __device__ float g_kb   [N_TOK*CT];
static __device__ float g_vb   [N_TOK*CT];
static __device__ float g_gpre [N_TOK*CT];
static __device__ float g_otmp [N_TOK*CT];
static __device__ float g_ptmp [N_TOK*CT];
static __device__ float g_hb   [N_TOK*2*CT];
static __device__ float g_zn   [N_TOK*KTOT*CP];
static __device__ int   g_idx  [N_TOK*KTOT];
static __device__ float g_wbf  [CP*NH];
static __device__ float g_b0   [NH];

__device__ __forceinline__ float sigmoidf_(float x) { return 1.0f / (1.0f + expf(-x)); }

__device__ __forceinline__ unsigned f2tf32(float x) {
    unsigned r; asm("cvt.rna.tf32.f32 %0, %1;" : "=r"(r) : "f"(x)); return r;
}

__device__ __forceinline__ void mma_tf32(float* c, const unsigned* a, const unsigned* b) {
    asm volatile(
        "mma.sync.aligned.m16n8k8.row.col.f32.tf32.tf32.f32 "
        "{%0,%1,%2,%3},{%4,%5,%6,%7},{%8,%9},{%0,%1,%2,%3};\n"
        : "+f"(c[0]), "+f"(c[1]), "+f"(c[2]), "+f"(c[3])
        : "r"(a[0]), "r"(a[1]), "r"(a[2]), "r"(a[3]), "r"(b[0]), "r"(b[1]));
}

// ---------------------------------------------------------------------------
// kNN indices: warp-per-token iterative extract-min with (dist,idx) packed keys.
// Tie-break: lowest index (matches jax.lax.top_k on -d2). Set equality is all
// that matters downstream (softmax is permutation-invariant over keys).
// ---------------------------------------------------------------------------
__global__ void idx_kernel(const float* __restrict__ X, int* __restrict__ idx) {
    __shared__ float xs0[N_TOK], xs1[N_TOK], xs2[N_TOK];
    int tid = threadIdx.x;
    for (int j = tid; j < N_TOK; j += 256) {
        xs0[j] = X[j*3+0]; xs1[j] = X[j*3+1]; xs2[j] = X[j*3+2];
    }
    __syncthreads();
    int lane = tid & 31, warp = tid >> 5;
    int n = blockIdx.x*8 + warp;
    if (lane < NLOC) {
        int v = n - NLOC/2 + lane;
        idx[n*KTOT + lane] = min(max(v, 0), N_TOK-1);
    }
    float x0 = xs0[n], x1 = xs1[n], x2 = xs2[n];

    unsigned removed = 0;
    unsigned long long bk = 0xFFFFFFFFFFFFFFFFull;
#pragma unroll
    for (int t = 0; t < 32; t++) {
        int j = lane + (t << 5);
        float d0 = x0 - xs0[j], d1 = x1 - xs1[j], d2 = x2 - xs2[j];
        float dd = d0*d0 + d1*d1 + d2*d2;
        unsigned long long k = ((unsigned long long)__float_as_uint(dd) << 32) | (unsigned)j;
        bk = min(bk, k);
    }
    for (int s = 0; s < NKNN; s++) {
        unsigned long long g = bk;
#pragma unroll
        for (int o = 16; o; o >>= 1) {
            unsigned long long other = __shfl_xor_sync(0xffffffffu, g, o);
            g = min(g, other);
        }
        int jstar = (int)(g & 0xffffffffu);
        if (lane == 0) idx[n*KTOT + NLOC + s] = jstar;
        if ((jstar & 31) == lane) {
            removed |= 1u << (jstar >> 5);
            bk = 0xFFFFFFFFFFFFFFFFull;
#pragma unroll
            for (int t = 0; t < 32; t++) {
                if (removed & (1u << t)) continue;
                int j = lane + (t << 5);
                float d0 = x0 - xs0[j], d1 = x1 - xs1[j], d2 = x2 - xs2[j];
                float dd = d0*d0 + d1*d1 + d2*d2;
                unsigned long long k = ((unsigned long long)__float_as_uint(dd) << 32) | (unsigned)j;
                bk = min(bk, k);
            }
        }
    }
}

// ---------------------------------------------------------------------------
// Gather pair reps + LayerNorm (no affine; affine folded into Wb later).
// ---------------------------------------------------------------------------
__global__ void zn_kernel(const float* __restrict__ Z, const int* __restrict__ idx,
                          float* __restrict__ zn) {
    int e = blockIdx.x * blockDim.x + threadIdx.x;
    if (e >= N_TOK*KTOT) return;
    int n = e / KTOT;
    int j = idx[e];
    const float* z = Z + ((size_t)n * N_TOK + j) * CP;
    float m = 0.f;
#pragma unroll
    for (int c = 0; c < CP; c++) m += z[c];
    m *= (1.0f/CP);
    float v = 0.f;
#pragma unroll
    for (int c = 0; c < CP; c++) { float d = z[c]-m; v += d*d; }
    v *= (1.0f/CP);
    float r = rsqrtf(v + 1e-5f);
#pragma unroll
    for (int c = 0; c < CP; c++) zn[(size_t)e*CP + c] = (z[c]-m)*r;
}

// ---------------------------------------------------------------------------
// Row LayerNorm, one block (128 thr) per row, single-pass sum+sumsq, row
// cached in registers. W in {384, 768}.
// ---------------------------------------------------------------------------
__global__ void ln_kernel(const float* __restrict__ X, const float* __restrict__ gamma,
                          float* __restrict__ Y, int W) {
    int n = blockIdx.x;
    int tid = threadIdx.x;
    const float* x = X + (size_t)n * W;
    int cnt = W >> 7;   // 3 or 6
    float v[6];
    float s = 0.f, s2 = 0.f;
    for (int i = 0; i < cnt; i++) {
        float t = x[tid + (i << 7)];
        v[i] = t; s += t; s2 += t*t;
    }
#pragma unroll
    for (int o = 16; o; o >>= 1) {
        s  += __shfl_xor_sync(0xffffffffu, s,  o);
        s2 += __shfl_xor_sync(0xffffffffu, s2, o);
    }
    __shared__ float ss[4], ss2[4];
    if ((tid & 31) == 0) { ss[tid >> 5] = s; ss2[tid >> 5] = s2; }
    __syncthreads();
    s  = ss[0]  + ss[1]  + ss[2]  + ss[3];
    s2 = ss2[0] + ss2[1] + ss2[2] + ss2[3];
    float m = s / W;
    float var = s2 / W - m*m;
    float r = rsqrtf(var + 1e-5f);
    for (int i = 0; i < cnt; i++) {
        int c = tid + (i << 7);
        float g = gamma ? gamma[c] : 1.0f;
        Y[(size_t)n*W + c] = (v[i]-m)*r*g;
    }
}

// ---------------------------------------------------------------------------
// Fold pair LN affine into Wb.
// ---------------------------------------------------------------------------
__global__ void fold_wb_kernel(const float* __restrict__ g, const float* __restrict__ b,
                               const float* __restrict__ Wb,
                               float* __restrict__ wbf, float* __restrict__ b0) {
    int t = threadIdx.x;
    if (t < CP*NH) {
        int c = t / NH;
        wbf[t] = g[c] * Wb[t];
    }
    if (t < NH) {
        float s = 0.f;
#pragma unroll
        for (int c = 0; c < CP; c++) s += b[c] * Wb[c*NH + t];
        b0[t] = s;
    }
}

// ---------------------------------------------------------------------------
// TF32 tensor-core GEMM, 64x64x16 tiles, 8 warps (2x4), warp tile 32x16,
// mma.sync m16n8k8 tf32, fp32 accum. Fused epilogues:
// MODE 0: C = acc1 + bias[c]                                (bias nullable)
// MODE 1: C = sigmoid(acc1+bias[c]) * extra + acc2           (adaLN dual)
// MODE 2: C += sigmoid(acc1+bias[c]) * extra                 (skip gate-add)
// MODE 3: C = silu(acc1) * acc2                              (SwiGLU dual)
// ---------------------------------------------------------------------------
#define BM 64
#define BN 64
#define BK 16

template<int MODE>
__global__ __launch_bounds__(256) void gemm_kernel(
        const float* __restrict__ A, const float* __restrict__ B1,
        const float* __restrict__ B2, const float* __restrict__ bias,
        const float* __restrict__ extra, float* __restrict__ C,
        int M, int N, int K) {
    constexpr bool DUAL = (MODE == 1 || MODE == 3);
    __shared__ unsigned As[BM][BK+4];                 // pad 20 -> conflict-free frags
    __shared__ unsigned Bs[BK][BN+8];                 // pad 72 -> conflict-free frags
    __shared__ unsigned Bs2[DUAL ? BK : 1][BN+8];

    int tid = threadIdx.x;
    int lane = tid & 31, warp = tid >> 5;
    int wm = warp >> 2, wn = warp & 3;                // 2 x 4 warp grid
    int lr = lane >> 2, lc = lane & 3;
    int row0 = blockIdx.y * BM, col0 = blockIdx.x * BN;

    int am = tid >> 2, ak = (tid & 3) << 2;           // A: 64 rows x 4 float4
    int bk_ = tid >> 4, bn_ = (tid & 15) << 2;        // B: 16 rows x 16 float4

    float acc [2][2][4] = {};
    float acc2[2][2][4] = {};

    for (int k0 = 0; k0 < K; k0 += BK) {
        float4 av = *(const float4*)(A + (size_t)(row0+am)*K + k0 + ak);
        As[am][ak+0] = f2tf32(av.x); As[am][ak+1] = f2tf32(av.y);
        As[am][ak+2] = f2tf32(av.z); As[am][ak+3] = f2tf32(av.w);
        float4 bv = *(const float4*)(B1 + (size_t)(k0+bk_)*N + col0 + bn_);
        Bs[bk_][bn_+0] = f2tf32(bv.x); Bs[bk_][bn_+1] = f2tf32(bv.y);
        Bs[bk_][bn_+2] = f2tf32(bv.z); Bs[bk_][bn_+3] = f2tf32(bv.w);
        if (DUAL) {
            float4 b2v = *(const float4*)(B2 + (size_t)(k0+bk_)*N + col0 + bn_);
            Bs2[bk_][bn_+0] = f2tf32(b2v.x); Bs2[bk_][bn_+1] = f2tf32(b2v.y);
            Bs2[bk_][bn_+2] = f2tf32(b2v.z); Bs2[bk_][bn_+3] = f2tf32(b2v.w);
        }
        __syncthreads();

#pragma unroll
        for (int ks = 0; ks < BK; ks += 8) {
            unsigned a[2][4], b[2][2], b2[2][2];
#pragma unroll
            for (int mi = 0; mi < 2; mi++) {
                int mr = wm*32 + mi*16 + lr;
                a[mi][0] = As[mr  ][ks+lc  ];
                a[mi][1] = As[mr+8][ks+lc  ];
                a[mi][2] = As[mr  ][ks+lc+4];
                a[mi][3] = As[mr+8][ks+lc+4];
            }
#pragma unroll
            for (int ni = 0; ni < 2; ni++) {
                int nc = wn*16 + ni*8 + lr;
                b[ni][0] = Bs[ks+lc  ][nc];
                b[ni][1] = Bs[ks+lc+4][nc];
                if (DUAL) {
                    b2[ni][0] = Bs2[ks+lc  ][nc];
                    b2[ni][1] = Bs2[ks+lc+4][nc];
                }
            }
#pragma unroll
            for (int mi = 0; mi < 2; mi++)
#pragma unroll
                for (int ni = 0; ni < 2; ni++) {
                    mma_tf32(acc[mi][ni], a[mi], b[ni]);
                    if (DUAL) mma_tf32(acc2[mi][ni], a[mi], b2[ni]);
                }
        }
        __syncthreads();
    }

#pragma unroll
    for (int mi = 0; mi < 2; mi++) {
#pragma unroll
        for (int half = 0; half < 2; half++) {
            int r = row0 + wm*32 + mi*16 + lr + half*8;
#pragma unroll
            for (int ni = 0; ni < 2; ni++) {
                int cidx = col0 + wn*16 + ni*8 + 2*lc;
                size_t off = (size_t)r*N + cidx;
                float v0 = acc[mi][ni][half*2+0];
                float v1 = acc[mi][ni][half*2+1];
                float2 out;
                if (MODE == 0) {
                    float b0v = bias ? bias[cidx]   : 0.0f;
                    float b1v = bias ? bias[cidx+1] : 0.0f;
                    out.x = v0 + b0v; out.y = v1 + b1v;
                    *(float2*)(C + off) = out;
                } else if (MODE == 1) {
                    float2 ex = *(const float2*)(extra + off);
                    out.x = sigmoidf_(v0 + bias[cidx  ]) * ex.x + acc2[mi][ni][half*2+0];
                    out.y = sigmoidf_(v1 + bias[cidx+1]) * ex.y + acc2[mi][ni][half*2+1];
                    *(float2*)(C + off) = out;
                } else if (MODE == 2) {
                    float2 ex = *(const float2*)(extra + off);
                    float2 cv = *(const float2*)(C + off);
                    cv.x += sigmoidf_(v0 + bias[cidx  ]) * ex.x;
                    cv.y += sigmoidf_(v1 + bias[cidx+1]) * ex.y;
                    *(float2*)(C + off) = cv;
                } else { // MODE 3
                    out.x = v0 * sigmoidf_(v0) * acc2[mi][ni][half*2+0];
                    out.y = v1 * sigmoidf_(v1) * acc2[mi][ni][half*2+1];
                    *(float2*)(C + off) = out;
                }
            }
        }
    }
}

// ---------------------------------------------------------------------------
// Attention: per-token block. 16 heads x 40 keys, pair bias, softmax,
// weighted V sum, per-channel sigmoid gate (gpre).
// ---------------------------------------------------------------------------
__global__ void attn_kernel(const float* __restrict__ q, const float* __restrict__ kb,
                            const float* __restrict__ vb, const float* __restrict__ gpre,
                            const int* __restrict__ idx, const float* __restrict__ zn,
                            const float* __restrict__ wbf, const float* __restrict__ b0,
                            float* __restrict__ out) {
    const float SCALE = 0.14433756729740643f; // 1/sqrt(48)
    int n = blockIdx.x;
    int tid = threadIdx.x;
    __shared__ float qs[CT];
    __shared__ float zs[KTOT*CP];
    __shared__ int   js[KTOT];
    __shared__ float sc[NH*KTOT];

    for (int c = tid; c < CT; c += 256) qs[c] = q[(size_t)n*CT + c];
    if (tid < KTOT) js[tid] = idx[n*KTOT + tid];
    for (int c = tid; c < KTOT*CP; c += 256) zs[c] = zn[(size_t)n*KTOT*CP + c];
    __syncthreads();

    for (int e = tid; e < NH*KTOT; e += 256) {
        int h = e / KTOT, k = e % KTOT;
        int j = js[k];
        const float* kp = kb + (size_t)j*CT + h*DH;
        const float* qp = qs + h*DH;
        float s = 0.f;
#pragma unroll
        for (int d = 0; d < DH; d++) s += qp[d]*kp[d];
        s *= SCALE;
        float bb = b0[h];
        const float* zp = zs + k*CP;
#pragma unroll
        for (int c = 0; c < CP; c++) bb += zp[c]*wbf[c*NH + h];
        sc[e] = s + bb;
    }
    __syncthreads();

    if (tid < NH) {
        int h = tid;
        float mx = -FLT_MAX;
        for (int k = 0; k < KTOT; k++) mx = fmaxf(mx, sc[h*KTOT + k]);
        float sum = 0.f;
        for (int k = 0; k < KTOT; k++) {
            float ex = expf(sc[h*KTOT + k] - mx);
            sc[h*KTOT + k] = ex; sum += ex;
        }
        float inv = 1.0f / sum;
        for (int k = 0; k < KTOT; k++) sc[h*KTOT + k] *= inv;
    }
    __syncthreads();

    for (int c = tid; c < CT; c += 256) {
        int h = c / DH;
        float acc = 0.f;
#pragma unroll 8
        for (int k = 0; k < KTOT; k++)
            acc += sc[h*KTOT + k] * vb[(size_t)js[k]*CT + c];
        float g = gpre[(size_t)n*CT + c];
        out[(size_t)n*CT + c] = acc * sigmoidf_(g);
    }
}

// ---------------------------------------------------------------------------
extern "C" void kernel_launch(void* const* d_in, const int* in_sizes, int n_in,
                              void* d_out, int out_size) {
    const float* A_I      = (const float*)d_in[0];
    const float* S        = (const float*)d_in[1];
    const float* Z        = (const float*)d_in[2];
    const float* X_L      = (const float*)d_in[3];
    const float* aln1_g   = (const float*)d_in[5];
    const float* aln1_sw  = (const float*)d_in[6];
    const float* aln1_sb  = (const float*)d_in[7];
    const float* aln1_shw = (const float*)d_in[8];
    const float* Wq       = (const float*)d_in[9];
    const float* bq       = (const float*)d_in[10];
    const float* Wk       = (const float*)d_in[11];
    const float* Wv       = (const float*)d_in[12];
    const float* plg      = (const float*)d_in[13];
    const float* plb      = (const float*)d_in[14];
    const float* Wb       = (const float*)d_in[15];
    const float* Wg       = (const float*)d_in[16];
    const float* Wo       = (const float*)d_in[17];
    const float* sgw      = (const float*)d_in[18];
    const float* sgb      = (const float*)d_in[19];
    const float* aln2_g   = (const float*)d_in[20];
    const float* aln2_sw  = (const float*)d_in[21];
    const float* aln2_sb  = (const float*)d_in[22];
    const float* aln2_shw = (const float*)d_in[23];
    const float* tw1      = (const float*)d_in[24];
    const float* tw2      = (const float*)d_in[25];
    const float* tw3      = (const float*)d_in[26];
    const float* tsgw     = (const float*)d_in[27];
    const float* tsgb     = (const float*)d_in[28];

    float* A = (float*)d_out;

    float *sn, *normA, *an, *q, *kb, *vb, *gpre, *otmp, *ptmp, *hb, *zn, *wbf, *b0;
    int* idx;
    cudaGetSymbolAddress((void**)&sn,    g_sn);
    cudaGetSymbolAddress((void**)&normA, g_normA);
    cudaGetSymbolAddress((void**)&an,    g_an);
    cudaGetSymbolAddress((void**)&q,     g_q);
    cudaGetSymbolAddress((void**)&kb,    g_kb);
    cudaGetSymbolAddress((void**)&vb,    g_vb);
    cudaGetSymbolAddress((void**)&gpre,  g_gpre);
    cudaGetSymbolAddress((void**)&otmp,  g_otmp);
    cudaGetSymbolAddress((void**)&ptmp,  g_ptmp);
    cudaGetSymbolAddress((void**)&hb,    g_hb);
    cudaGetSymbolAddress((void**)&zn,    g_zn);
    cudaGetSymbolAddress((void**)&wbf,   g_wbf);
    cudaGetSymbolAddress((void**)&b0,    g_b0);
    cudaGetSymbolAddress((void**)&idx,   g_idx);

    cudaMemcpyAsync(A, A_I, (size_t)N_TOK*CT*sizeof(float), cudaMemcpyDeviceToDevice, 0);

    idx_kernel<<<N_TOK/8, 256>>>(X_L, idx);
    zn_kernel<<<(N_TOK*KTOT + 255)/256, 256>>>(Z, idx, zn);

    dim3 g768(CT/BN, N_TOK/BM);
    dim3 g1536(2*CT/BN, N_TOK/BM);

    for (int i = 0; i < NB; i++) {
        size_t wo_ct  = (size_t)i*CT*CT;
        size_t wo_cs  = (size_t)i*CS*CT;
        size_t wo_t12 = (size_t)i*CT*2*CT;
        size_t wo_t3  = (size_t)i*2*CT*CT;

        // --- LocalAttentionPairBias ---
        ln_kernel<<<N_TOK, 128>>>(S, aln1_g + i*CS, sn, CS);
        ln_kernel<<<N_TOK, 128>>>(A, nullptr, normA, CT);
        gemm_kernel<1><<<g768, 256>>>(sn, aln1_sw + wo_cs, aln1_shw + wo_cs,
                                      aln1_sb + i*CT, normA, an, N_TOK, CT, CS);
        gemm_kernel<0><<<g768, 256>>>(an, Wq + wo_ct, nullptr, bq + i*CT, nullptr, q,  N_TOK, CT, CT);
        gemm_kernel<0><<<g768, 256>>>(an, Wk + wo_ct, nullptr, nullptr,   nullptr, kb, N_TOK, CT, CT);
        gemm_kernel<0><<<g768, 256>>>(an, Wv + wo_ct, nullptr, nullptr,   nullptr, vb, N_TOK, CT, CT);
        gemm_kernel<0><<<g768, 256>>>(an, Wg + wo_ct, nullptr, nullptr,   nullptr, gpre, N_TOK, CT, CT);
        fold_wb_kernel<<<1, 256>>>(plg + i*CP, plb + i*CP, Wb + i*CP*NH, wbf, b0);
        attn_kernel<<<N_TOK, 256>>>(q, kb, vb, gpre, idx, zn, wbf, b0, otmp);
        gemm_kernel<0><<<g768, 256>>>(otmp, Wo + wo_ct, nullptr, nullptr, nullptr, ptmp, N_TOK, CT, CT);
        gemm_kernel<2><<<g768, 256>>>(S, sgw + wo_cs, nullptr, sgb + i*CT, ptmp, A, N_TOK, CT, CS);

        // --- ConditionedTransitionBlock ---
        ln_kernel<<<N_TOK, 128>>>(S, aln2_g + i*CS, sn, CS);
        ln_kernel<<<N_TOK, 128>>>(A, nullptr, normA, CT);
        gemm_kernel<1><<<g768, 256>>>(sn, aln2_sw + wo_cs, aln2_shw + wo_cs,
                                      aln2_sb + i*CT, normA, an, N_TOK, CT, CS);
        gemm_kernel<3><<<g1536, 256>>>(an, tw1 + wo_t12, tw2 + wo_t12, nullptr, nullptr,
                                       hb, N_TOK, 2*CT, CT);
        gemm_kernel<0><<<g768, 256>>>(hb, tw3 + wo_t3, nullptr, nullptr, nullptr, ptmp, N_TOK, CT, 2*CT);
        gemm_kernel<2><<<g768, 256>>>(S, tsgw + wo_cs, nullptr, tsgb + i*CT, ptmp, A, N_TOK, CT, CS);
    }
}

// round 7
// speedup vs baseline: 3.5734x; 1.2347x over previous
#include <cuda_runtime.h>
#include <math.h>
#include <float.h>

#define N_TOK 1024
#define CT    768
#define CS    384
#define CP    16
#define NH    16
#define DH    48
#define NB    4
#define NLOC  8
#define NKNN  32
#define KTOT  40

static __device__ float g_sn   [N_TOK*CS];
static __device__ float g_normA[N_TOK*CT];
static __device__ float g_an   [N_TOK*CT];
static __device__ float g_q    [N_TOK*CT];
static __device__ float g_kb   [N_TOK*CT];
static __device__ float g_vb   [N_TOK*CT];
static __device__ float g_gpre [N_TOK*CT];
static __device__ float g_otmp [N_TOK*CT];
static __device__ float g_ptmp [N_TOK*CT];
static __device__ float g_hb   [N_TOK*2*CT];
static __device__ float g_zn   [N_TOK*KTOT*CP];
static __device__ int   g_idx  [N_TOK*KTOT];
static __device__ float g_wbf  [CP*NH];
static __device__ float g_b0   [NH];

__device__ __forceinline__ float sigmoidf_(float x) { return 1.0f / (1.0f + expf(-x)); }

__device__ __forceinline__ unsigned f2tf32(float x) {
    unsigned r; asm("cvt.rna.tf32.f32 %0, %1;" : "=r"(r) : "f"(x)); return r;
}

__device__ __forceinline__ void mma_tf32(float* c, const unsigned* a, const unsigned* b) {
    asm volatile(
        "mma.sync.aligned.m16n8k8.row.col.f32.tf32.tf32.f32 "
        "{%0,%1,%2,%3},{%4,%5,%6,%7},{%8,%9},{%0,%1,%2,%3};\n"
        : "+f"(c[0]), "+f"(c[1]), "+f"(c[2]), "+f"(c[3])
        : "r"(a[0]), "r"(a[1]), "r"(a[2]), "r"(a[3]), "r"(b[0]), "r"(b[1]));
}

// ---------------------------------------------------------------------------
// kNN indices: warp-per-token iterative extract-min with (dist,idx) packed keys.
// ---------------------------------------------------------------------------
__global__ void idx_kernel(const float* __restrict__ X, int* __restrict__ idx) {
    __shared__ float xs0[N_TOK], xs1[N_TOK], xs2[N_TOK];
    int tid = threadIdx.x;
    for (int j = tid; j < N_TOK; j += 256) {
        xs0[j] = X[j*3+0]; xs1[j] = X[j*3+1]; xs2[j] = X[j*3+2];
    }
    __syncthreads();
    int lane = tid & 31, warp = tid >> 5;
    int n = blockIdx.x*8 + warp;
    if (lane < NLOC) {
        int v = n - NLOC/2 + lane;
        idx[n*KTOT + lane] = min(max(v, 0), N_TOK-1);
    }
    float x0 = xs0[n], x1 = xs1[n], x2 = xs2[n];

    unsigned removed = 0;
    unsigned long long bk = 0xFFFFFFFFFFFFFFFFull;
#pragma unroll
    for (int t = 0; t < 32; t++) {
        int j = lane + (t << 5);
        float d0 = x0 - xs0[j], d1 = x1 - xs1[j], d2 = x2 - xs2[j];
        float dd = d0*d0 + d1*d1 + d2*d2;
        unsigned long long k = ((unsigned long long)__float_as_uint(dd) << 32) | (unsigned)j;
        bk = min(bk, k);
    }
    for (int s = 0; s < NKNN; s++) {
        unsigned long long g = bk;
#pragma unroll
        for (int o = 16; o; o >>= 1) {
            unsigned long long other = __shfl_xor_sync(0xffffffffu, g, o);
            g = min(g, other);
        }
        int jstar = (int)(g & 0xffffffffu);
        if (lane == 0) idx[n*KTOT + NLOC + s] = jstar;
        if ((jstar & 31) == lane) {
            removed |= 1u << (jstar >> 5);
            bk = 0xFFFFFFFFFFFFFFFFull;
#pragma unroll
            for (int t = 0; t < 32; t++) {
                if (removed & (1u << t)) continue;
                int j = lane + (t << 5);
                float d0 = x0 - xs0[j], d1 = x1 - xs1[j], d2 = x2 - xs2[j];
                float dd = d0*d0 + d1*d1 + d2*d2;
                unsigned long long k = ((unsigned long long)__float_as_uint(dd) << 32) | (unsigned)j;
                bk = min(bk, k);
            }
        }
    }
}

// ---------------------------------------------------------------------------
// Gather pair reps + LayerNorm (affine folded into Wb later).
// ---------------------------------------------------------------------------
__global__ void zn_kernel(const float* __restrict__ Z, const int* __restrict__ idx,
                          float* __restrict__ zn) {
    int e = blockIdx.x * blockDim.x + threadIdx.x;
    if (e >= N_TOK*KTOT) return;
    int n = e / KTOT;
    int j = idx[e];
    const float* z = Z + ((size_t)n * N_TOK + j) * CP;
    float m = 0.f;
#pragma unroll
    for (int c = 0; c < CP; c++) m += z[c];
    m *= (1.0f/CP);
    float v = 0.f;
#pragma unroll
    for (int c = 0; c < CP; c++) { float d = z[c]-m; v += d*d; }
    v *= (1.0f/CP);
    float r = rsqrtf(v + 1e-5f);
#pragma unroll
    for (int c = 0; c < CP; c++) zn[(size_t)e*CP + c] = (z[c]-m)*r;
}

// ---------------------------------------------------------------------------
// Row LayerNorm.
// ---------------------------------------------------------------------------
__global__ void ln_kernel(const float* __restrict__ X, const float* __restrict__ gamma,
                          float* __restrict__ Y, int W) {
    int n = blockIdx.x;
    int tid = threadIdx.x;
    const float* x = X + (size_t)n * W;
    int cnt = W >> 7;   // 3 or 6
    float v[6];
    float s = 0.f, s2 = 0.f;
    for (int i = 0; i < cnt; i++) {
        float t = x[tid + (i << 7)];
        v[i] = t; s += t; s2 += t*t;
    }
#pragma unroll
    for (int o = 16; o; o >>= 1) {
        s  += __shfl_xor_sync(0xffffffffu, s,  o);
        s2 += __shfl_xor_sync(0xffffffffu, s2, o);
    }
    __shared__ float ss[4], ss2[4];
    if ((tid & 31) == 0) { ss[tid >> 5] = s; ss2[tid >> 5] = s2; }
    __syncthreads();
    s  = ss[0]  + ss[1]  + ss[2]  + ss[3];
    s2 = ss2[0] + ss2[1] + ss2[2] + ss2[3];
    float m = s / W;
    float var = s2 / W - m*m;
    float r = rsqrtf(var + 1e-5f);
    for (int i = 0; i < cnt; i++) {
        int c = tid + (i << 7);
        float g = gamma ? gamma[c] : 1.0f;
        Y[(size_t)n*W + c] = (v[i]-m)*r*g;
    }
}

// ---------------------------------------------------------------------------
// Fold pair LN affine into Wb.
// ---------------------------------------------------------------------------
__global__ void fold_wb_kernel(const float* __restrict__ g, const float* __restrict__ b,
                               const float* __restrict__ Wb,
                               float* __restrict__ wbf, float* __restrict__ b0) {
    int t = threadIdx.x;
    if (t < CP*NH) {
        int c = t / NH;
        wbf[t] = g[c] * Wb[t];
    }
    if (t < NH) {
        float s = 0.f;
#pragma unroll
        for (int c = 0; c < CP; c++) s += b[c] * Wb[c*NH + t];
        b0[t] = s;
    }
}

// ---------------------------------------------------------------------------
// TF32 tensor-core GEMM, 64x64x32 tiles, double-buffered DYNAMIC smem with
// register prefetch: LDG(next) -> MMA(cur) -> cvt+STS(next) -> 1 barrier.
// 8 warps (2x4), warp tile 32x16, mma m16n8k8 tf32, fp32 accum.
// MODE 0: C = acc1 + bias[c]                                (bias nullable)
// MODE 1: C = sigmoid(acc1+bias[c]) * extra + acc2           (adaLN dual)
// MODE 2: C += sigmoid(acc1+bias[c]) * extra                 (skip gate-add)
// MODE 3: C = silu(acc1) * acc2                              (SwiGLU dual)
// ---------------------------------------------------------------------------
#define BM 64
#define BN 64
#define BK 32
#define APAD 4
#define BPAD 8
// dynamic smem sizes (unsigned words)
#define AS_WORDS (2*BM*(BK+APAD))
#define BS_WORDS (2*BK*(BN+BPAD))
#define SMEM_WORDS_SINGLE (AS_WORDS + BS_WORDS)
#define SMEM_WORDS_DUAL   (AS_WORDS + 2*BS_WORDS)
#define SMEM_BYTES_SINGLE (SMEM_WORDS_SINGLE*4)
#define SMEM_BYTES_DUAL   (SMEM_WORDS_DUAL*4)

template<int MODE>
__device__ __forceinline__ void gemm_body(
        const float* __restrict__ A, const float* __restrict__ B1,
        const float* __restrict__ B2, const float* __restrict__ bias,
        const float* __restrict__ extra, float* __restrict__ C,
        int M, int N, int K) {
    constexpr bool DUAL = (MODE == 1 || MODE == 3);
    extern __shared__ unsigned smem_u[];
    typedef unsigned AsT[BM][BK+APAD];
    typedef unsigned BsT[BK][BN+BPAD];
    AsT* As  = reinterpret_cast<AsT*>(smem_u);                     // [2][BM][BK+APAD]
    BsT* Bs  = reinterpret_cast<BsT*>(smem_u + AS_WORDS);          // [2][BK][BN+BPAD]
    BsT* Bs2 = reinterpret_cast<BsT*>(smem_u + AS_WORDS + BS_WORDS);

    int tid = threadIdx.x;
    int lane = tid & 31, warp = tid >> 5;
    int wm = warp >> 2, wn = warp & 3;                // 2 x 4 warp grid
    int lr = lane >> 2, lc = lane & 3;
    int row0 = blockIdx.y * BM, col0 = blockIdx.x * BN;

    // ldg mapping: A 64 rows x 32 k -> thread = (row, 8-float chunk)
    int arow = tid >> 2, ac = (tid & 3) << 3;
    // B 32 k-rows x 64 n -> thread = (k-row, 8-float chunk)
    int brow = tid >> 3, bc = (tid & 7) << 3;

    const float* Ag  = A  + (size_t)(row0 + arow)*K + ac;
    const float* B1g = B1 + (size_t)brow*N + col0 + bc;
    const float* B2g = DUAL ? (B2 + (size_t)brow*N + col0 + bc) : nullptr;

    float4 ra0, ra1, rb0, rb1, rc0, rc1;

    auto ldg = [&](int k0) {
        ra0 = *(const float4*)(Ag + k0);
        ra1 = *(const float4*)(Ag + k0 + 4);
        rb0 = *(const float4*)(B1g + (size_t)k0*N);
        rb1 = *(const float4*)(B1g + (size_t)k0*N + 4);
        if (DUAL) {
            rc0 = *(const float4*)(B2g + (size_t)k0*N);
            rc1 = *(const float4*)(B2g + (size_t)k0*N + 4);
        }
    };
    auto sts = [&](int s) {
        *(uint4*)&As[s][arow][ac]   = make_uint4(f2tf32(ra0.x), f2tf32(ra0.y), f2tf32(ra0.z), f2tf32(ra0.w));
        *(uint4*)&As[s][arow][ac+4] = make_uint4(f2tf32(ra1.x), f2tf32(ra1.y), f2tf32(ra1.z), f2tf32(ra1.w));
        *(uint4*)&Bs[s][brow][bc]   = make_uint4(f2tf32(rb0.x), f2tf32(rb0.y), f2tf32(rb0.z), f2tf32(rb0.w));
        *(uint4*)&Bs[s][brow][bc+4] = make_uint4(f2tf32(rb1.x), f2tf32(rb1.y), f2tf32(rb1.z), f2tf32(rb1.w));
        if (DUAL) {
            *(uint4*)&Bs2[s][brow][bc]   = make_uint4(f2tf32(rc0.x), f2tf32(rc0.y), f2tf32(rc0.z), f2tf32(rc0.w));
            *(uint4*)&Bs2[s][brow][bc+4] = make_uint4(f2tf32(rc1.x), f2tf32(rc1.y), f2tf32(rc1.z), f2tf32(rc1.w));
        }
    };

    float acc [2][2][4] = {};
    float acc2[2][2][4] = {};

    int NIT = K / BK;
    ldg(0);
    sts(0);
    __syncthreads();

    for (int it = 0; it < NIT; it++) {
        int s = it & 1;
        if (it + 1 < NIT) ldg((it + 1) * BK);

#pragma unroll
        for (int ks = 0; ks < BK; ks += 8) {
            unsigned a[2][4], b[2][2], b2[2][2];
#pragma unroll
            for (int mi = 0; mi < 2; mi++) {
                int mr = wm*32 + mi*16 + lr;
                a[mi][0] = As[s][mr  ][ks+lc  ];
                a[mi][1] = As[s][mr+8][ks+lc  ];
                a[mi][2] = As[s][mr  ][ks+lc+4];
                a[mi][3] = As[s][mr+8][ks+lc+4];
            }
#pragma unroll
            for (int ni = 0; ni < 2; ni++) {
                int nc = wn*16 + ni*8 + lr;
                b[ni][0] = Bs[s][ks+lc  ][nc];
                b[ni][1] = Bs[s][ks+lc+4][nc];
                if (DUAL) {
                    b2[ni][0] = Bs2[s][ks+lc  ][nc];
                    b2[ni][1] = Bs2[s][ks+lc+4][nc];
                }
            }
#pragma unroll
            for (int mi = 0; mi < 2; mi++)
#pragma unroll
                for (int ni = 0; ni < 2; ni++) {
                    mma_tf32(acc[mi][ni], a[mi], b[ni]);
                    if (DUAL) mma_tf32(acc2[mi][ni], a[mi], b2[ni]);
                }
        }

        if (it + 1 < NIT) sts((it + 1) & 1);
        __syncthreads();
    }

#pragma unroll
    for (int mi = 0; mi < 2; mi++) {
#pragma unroll
        for (int half = 0; half < 2; half++) {
            int r = row0 + wm*32 + mi*16 + lr + half*8;
#pragma unroll
            for (int ni = 0; ni < 2; ni++) {
                int cidx = col0 + wn*16 + ni*8 + 2*lc;
                size_t off = (size_t)r*N + cidx;
                float v0 = acc[mi][ni][half*2+0];
                float v1 = acc[mi][ni][half*2+1];
                float2 out;
                if (MODE == 0) {
                    float b0v = bias ? bias[cidx]   : 0.0f;
                    float b1v = bias ? bias[cidx+1] : 0.0f;
                    out.x = v0 + b0v; out.y = v1 + b1v;
                    *(float2*)(C + off) = out;
                } else if (MODE == 1) {
                    float2 ex = *(const float2*)(extra + off);
                    out.x = sigmoidf_(v0 + bias[cidx  ]) * ex.x + acc2[mi][ni][half*2+0];
                    out.y = sigmoidf_(v1 + bias[cidx+1]) * ex.y + acc2[mi][ni][half*2+1];
                    *(float2*)(C + off) = out;
                } else if (MODE == 2) {
                    float2 ex = *(const float2*)(extra + off);
                    float2 cv = *(const float2*)(C + off);
                    cv.x += sigmoidf_(v0 + bias[cidx  ]) * ex.x;
                    cv.y += sigmoidf_(v1 + bias[cidx+1]) * ex.y;
                    *(float2*)(C + off) = cv;
                } else { // MODE 3
                    out.x = v0 * sigmoidf_(v0) * acc2[mi][ni][half*2+0];
                    out.y = v1 * sigmoidf_(v1) * acc2[mi][ni][half*2+1];
                    *(float2*)(C + off) = out;
                }
            }
        }
    }
}

template<int MODE>
__global__ __launch_bounds__(256) void gemm_kernel(
        const float* __restrict__ A, const float* __restrict__ B1,
        const float* __restrict__ B2, const float* __restrict__ bias,
        const float* __restrict__ extra, float* __restrict__ C,
        int M, int N, int K) {
    gemm_body<MODE>(A, B1, B2, bias, extra, C, M, N, K);
}

// 4 MODE-0 GEMMs (same A) in one launch, selected by blockIdx.z.
struct QuadParams {
    const float* B[4];
    const float* bias[4];
    float* C[4];
};

__global__ __launch_bounds__(256) void gemm_quad_kernel(
        const float* __restrict__ A, QuadParams p, int M, int N, int K) {
    int z = blockIdx.z;
    gemm_body<0>(A, p.B[z], nullptr, p.bias[z], nullptr, p.C[z], M, N, K);
}

// ---------------------------------------------------------------------------
// Attention: per-token block. 16 heads x 40 keys, pair bias, softmax,
// weighted V sum, per-channel sigmoid gate (gpre).
// ---------------------------------------------------------------------------
__global__ void attn_kernel(const float* __restrict__ q, const float* __restrict__ kb,
                            const float* __restrict__ vb, const float* __restrict__ gpre,
                            const int* __restrict__ idx, const float* __restrict__ zn,
                            const float* __restrict__ wbf, const float* __restrict__ b0,
                            float* __restrict__ out) {
    const float SCALE = 0.14433756729740643f; // 1/sqrt(48)
    int n = blockIdx.x;
    int tid = threadIdx.x;
    __shared__ float qs[CT];
    __shared__ float zs[KTOT*CP];
    __shared__ int   js[KTOT];
    __shared__ float sc[NH*KTOT];

    for (int c = tid; c < CT; c += 256) qs[c] = q[(size_t)n*CT + c];
    if (tid < KTOT) js[tid] = idx[n*KTOT + tid];
    for (int c = tid; c < KTOT*CP; c += 256) zs[c] = zn[(size_t)n*KTOT*CP + c];
    __syncthreads();

    for (int e = tid; e < NH*KTOT; e += 256) {
        int h = e / KTOT, k = e % KTOT;
        int j = js[k];
        const float* kp = kb + (size_t)j*CT + h*DH;
        const float* qp = qs + h*DH;
        float s = 0.f;
#pragma unroll
        for (int d = 0; d < DH; d++) s += qp[d]*kp[d];
        s *= SCALE;
        float bb = b0[h];
        const float* zp = zs + k*CP;
#pragma unroll
        for (int c = 0; c < CP; c++) bb += zp[c]*wbf[c*NH + h];
        sc[e] = s + bb;
    }
    __syncthreads();

    if (tid < NH) {
        int h = tid;
        float mx = -FLT_MAX;
        for (int k = 0; k < KTOT; k++) mx = fmaxf(mx, sc[h*KTOT + k]);
        float sum = 0.f;
        for (int k = 0; k < KTOT; k++) {
            float ex = expf(sc[h*KTOT + k] - mx);
            sc[h*KTOT + k] = ex; sum += ex;
        }
        float inv = 1.0f / sum;
        for (int k = 0; k < KTOT; k++) sc[h*KTOT + k] *= inv;
    }
    __syncthreads();

    for (int c = tid; c < CT; c += 256) {
        int h = c / DH;
        float acc = 0.f;
#pragma unroll 8
        for (int k = 0; k < KTOT; k++)
            acc += sc[h*KTOT + k] * vb[(size_t)js[k]*CT + c];
        float g = gpre[(size_t)n*CT + c];
        out[(size_t)n*CT + c] = acc * sigmoidf_(g);
    }
}

// ---------------------------------------------------------------------------
extern "C" void kernel_launch(void* const* d_in, const int* in_sizes, int n_in,
                              void* d_out, int out_size) {
    const float* A_I      = (const float*)d_in[0];
    const float* S        = (const float*)d_in[1];
    const float* Z        = (const float*)d_in[2];
    const float* X_L      = (const float*)d_in[3];
    const float* aln1_g   = (const float*)d_in[5];
    const float* aln1_sw  = (const float*)d_in[6];
    const float* aln1_sb  = (const float*)d_in[7];
    const float* aln1_shw = (const float*)d_in[8];
    const float* Wq       = (const float*)d_in[9];
    const float* bq       = (const float*)d_in[10];
    const float* Wk       = (const float*)d_in[11];
    const float* Wv       = (const float*)d_in[12];
    const float* plg      = (const float*)d_in[13];
    const float* plb      = (const float*)d_in[14];
    const float* Wb       = (const float*)d_in[15];
    const float* Wg       = (const float*)d_in[16];
    const float* Wo       = (const float*)d_in[17];
    const float* sgw      = (const float*)d_in[18];
    const float* sgb      = (const float*)d_in[19];
    const float* aln2_g   = (const float*)d_in[20];
    const float* aln2_sw  = (const float*)d_in[21];
    const float* aln2_sb  = (const float*)d_in[22];
    const float* aln2_shw = (const float*)d_in[23];
    const float* tw1      = (const float*)d_in[24];
    const float* tw2      = (const float*)d_in[25];
    const float* tw3      = (const float*)d_in[26];
    const float* tsgw     = (const float*)d_in[27];
    const float* tsgb     = (const float*)d_in[28];

    float* A = (float*)d_out;

    float *sn, *normA, *an, *q, *kb, *vb, *gpre, *otmp, *ptmp, *hb, *zn, *wbf, *b0;
    int* idx;
    cudaGetSymbolAddress((void**)&sn,    g_sn);
    cudaGetSymbolAddress((void**)&normA, g_normA);
    cudaGetSymbolAddress((void**)&an,    g_an);
    cudaGetSymbolAddress((void**)&q,     g_q);
    cudaGetSymbolAddress((void**)&kb,    g_kb);
    cudaGetSymbolAddress((void**)&vb,    g_vb);
    cudaGetSymbolAddress((void**)&gpre,  g_gpre);
    cudaGetSymbolAddress((void**)&otmp,  g_otmp);
    cudaGetSymbolAddress((void**)&ptmp,  g_ptmp);
    cudaGetSymbolAddress((void**)&hb,    g_hb);
    cudaGetSymbolAddress((void**)&zn,    g_zn);
    cudaGetSymbolAddress((void**)&wbf,   g_wbf);
    cudaGetSymbolAddress((void**)&b0,    g_b0);
    cudaGetSymbolAddress((void**)&idx,   g_idx);

    // Raise dynamic-smem ceiling for the DUAL instantiations (54 KB > 48 KB default).
    cudaFuncSetAttribute(gemm_kernel<1>, cudaFuncAttributeMaxDynamicSharedMemorySize, SMEM_BYTES_DUAL);
    cudaFuncSetAttribute(gemm_kernel<3>, cudaFuncAttributeMaxDynamicSharedMemorySize, SMEM_BYTES_DUAL);
    cudaFuncSetAttribute(gemm_kernel<0>, cudaFuncAttributeMaxDynamicSharedMemorySize, SMEM_BYTES_SINGLE);
    cudaFuncSetAttribute(gemm_kernel<2>, cudaFuncAttributeMaxDynamicSharedMemorySize, SMEM_BYTES_SINGLE);
    cudaFuncSetAttribute(gemm_quad_kernel, cudaFuncAttributeMaxDynamicSharedMemorySize, SMEM_BYTES_SINGLE);

    cudaMemcpyAsync(A, A_I, (size_t)N_TOK*CT*sizeof(float), cudaMemcpyDeviceToDevice, 0);

    idx_kernel<<<N_TOK/8, 256>>>(X_L, idx);
    zn_kernel<<<(N_TOK*KTOT + 255)/256, 256>>>(Z, idx, zn);

    dim3 g768(CT/BN, N_TOK/BM);
    dim3 g1536(2*CT/BN, N_TOK/BM);
    dim3 gq(CT/BN, N_TOK/BM, 4);

    for (int i = 0; i < NB; i++) {
        size_t wo_ct  = (size_t)i*CT*CT;
        size_t wo_cs  = (size_t)i*CS*CT;
        size_t wo_t12 = (size_t)i*CT*2*CT;
        size_t wo_t3  = (size_t)i*2*CT*CT;

        // --- LocalAttentionPairBias ---
        ln_kernel<<<N_TOK, 128>>>(S, aln1_g + i*CS, sn, CS);
        ln_kernel<<<N_TOK, 128>>>(A, nullptr, normA, CT);
        gemm_kernel<1><<<g768, 256, SMEM_BYTES_DUAL>>>(sn, aln1_sw + wo_cs, aln1_shw + wo_cs,
                                      aln1_sb + i*CT, normA, an, N_TOK, CT, CS);
        QuadParams qp;
        qp.B[0] = Wq + wo_ct; qp.bias[0] = bq + i*CT; qp.C[0] = q;
        qp.B[1] = Wk + wo_ct; qp.bias[1] = nullptr;   qp.C[1] = kb;
        qp.B[2] = Wv + wo_ct; qp.bias[2] = nullptr;   qp.C[2] = vb;
        qp.B[3] = Wg + wo_ct; qp.bias[3] = nullptr;   qp.C[3] = gpre;
        gemm_quad_kernel<<<gq, 256, SMEM_BYTES_SINGLE>>>(an, qp, N_TOK, CT, CT);
        fold_wb_kernel<<<1, 256>>>(plg + i*CP, plb + i*CP, Wb + i*CP*NH, wbf, b0);
        attn_kernel<<<N_TOK, 256>>>(q, kb, vb, gpre, idx, zn, wbf, b0, otmp);
        gemm_kernel<0><<<g768, 256, SMEM_BYTES_SINGLE>>>(otmp, Wo + wo_ct, nullptr, nullptr, nullptr, ptmp, N_TOK, CT, CT);
        gemm_kernel<2><<<g768, 256, SMEM_BYTES_SINGLE>>>(S, sgw + wo_cs, nullptr, sgb + i*CT, ptmp, A, N_TOK, CT, CS);

        // --- ConditionedTransitionBlock ---
        ln_kernel<<<N_TOK, 128>>>(S, aln2_g + i*CS, sn, CS);
        ln_kernel<<<N_TOK, 128>>>(A, nullptr, normA, CT);
        gemm_kernel<1><<<g768, 256, SMEM_BYTES_DUAL>>>(sn, aln2_sw + wo_cs, aln2_shw + wo_cs,
                                      aln2_sb + i*CT, normA, an, N_TOK, CT, CS);
        gemm_kernel<3><<<g1536, 256, SMEM_BYTES_DUAL>>>(an, tw1 + wo_t12, tw2 + wo_t12, nullptr, nullptr,
                                       hb, N_TOK, 2*CT, CT);
        gemm_kernel<0><<<g768, 256, SMEM_BYTES_SINGLE>>>(hb, tw3 + wo_t3, nullptr, nullptr, nullptr, ptmp, N_TOK, CT, 2*CT);
        gemm_kernel<2><<<g768, 256, SMEM_BYTES_SINGLE>>>(S, tsgw + wo_cs, nullptr, tsgb + i*CT, ptmp, A, N_TOK, CT, CS);
    }
}

// round 9
// speedup vs baseline: 4.2167x; 1.1800x over previous
#include <cuda_runtime.h>
#include <cuda_bf16.h>
#include <math.h>
#include <float.h>

#define N_TOK 1024
#define CT    768
#define CS    384
#define CP    16
#define NH    16
#define DH    48
#define NB    4
#define NLOC  8
#define NKNN  32
#define KTOT  40

static __device__ float g_sn   [N_TOK*CS];
static __device__ float g_normA[N_TOK*CT];
static __device__ float g_an   [N_TOK*CT];
static __device__ float g_q    [N_TOK*CT];
static __device__ float g_kb   [N_TOK*CT];
static __device__ float g_vb   [N_TOK*CT];
static __device__ float g_gpre [N_TOK*CT];
static __device__ float g_otmp [N_TOK*CT];
static __device__ float g_ptmp [N_TOK*CT];
static __device__ float g_hb   [N_TOK*2*CT];
static __device__ float g_zn   [N_TOK*KTOT*CP];
static __device__ int   g_idx  [N_TOK*KTOT];
static __device__ float g_wbf  [CP*NH];
static __device__ float g_b0   [NH];

__device__ __forceinline__ float sigmoidf_(float x) { return 1.0f / (1.0f + expf(-x)); }

__device__ __forceinline__ unsigned pk2bf(float x, float y) {
    __nv_bfloat162 t = __floats2bfloat162_rn(x, y);
    return *reinterpret_cast<unsigned*>(&t);
}

__device__ __forceinline__ unsigned sptr(const void* p) {
    return (unsigned)__cvta_generic_to_shared(p);
}

__device__ __forceinline__ void ldsm4(unsigned& r0, unsigned& r1, unsigned& r2, unsigned& r3,
                                      unsigned addr) {
    asm volatile("ldmatrix.sync.aligned.m8n8.x4.shared.b16 {%0,%1,%2,%3},[%4];"
                 : "=r"(r0), "=r"(r1), "=r"(r2), "=r"(r3) : "r"(addr));
}

__device__ __forceinline__ void ldsm4t(unsigned& r0, unsigned& r1, unsigned& r2, unsigned& r3,
                                       unsigned addr) {
    asm volatile("ldmatrix.sync.aligned.m8n8.x4.trans.shared.b16 {%0,%1,%2,%3},[%4];"
                 : "=r"(r0), "=r"(r1), "=r"(r2), "=r"(r3) : "r"(addr));
}

__device__ __forceinline__ void mma_bf16(float* c, const unsigned* a, unsigned b0, unsigned b1) {
    asm volatile(
        "mma.sync.aligned.m16n8k16.row.col.f32.bf16.bf16.f32 "
        "{%0,%1,%2,%3},{%4,%5,%6,%7},{%8,%9},{%0,%1,%2,%3};\n"
        : "+f"(c[0]), "+f"(c[1]), "+f"(c[2]), "+f"(c[3])
        : "r"(a[0]), "r"(a[1]), "r"(a[2]), "r"(a[3]), "r"(b0), "r"(b1));
}

// ---------------------------------------------------------------------------
// kNN indices: warp-per-token iterative extract-min with (dist,idx) packed keys.
// ---------------------------------------------------------------------------
__global__ void idx_kernel(const float* __restrict__ X, int* __restrict__ idx) {
    __shared__ float xs0[N_TOK], xs1[N_TOK], xs2[N_TOK];
    int tid = threadIdx.x;
    for (int j = tid; j < N_TOK; j += 256) {
        xs0[j] = X[j*3+0]; xs1[j] = X[j*3+1]; xs2[j] = X[j*3+2];
    }
    __syncthreads();
    int lane = tid & 31, warp = tid >> 5;
    int n = blockIdx.x*8 + warp;
    if (lane < NLOC) {
        int v = n - NLOC/2 + lane;
        idx[n*KTOT + lane] = min(max(v, 0), N_TOK-1);
    }
    float x0 = xs0[n], x1 = xs1[n], x2 = xs2[n];

    unsigned removed = 0;
    unsigned long long bk = 0xFFFFFFFFFFFFFFFFull;
#pragma unroll
    for (int t = 0; t < 32; t++) {
        int j = lane + (t << 5);
        float d0 = x0 - xs0[j], d1 = x1 - xs1[j], d2 = x2 - xs2[j];
        float dd = d0*d0 + d1*d1 + d2*d2;
        unsigned long long k = ((unsigned long long)__float_as_uint(dd) << 32) | (unsigned)j;
        bk = min(bk, k);
    }
    for (int s = 0; s < NKNN; s++) {
        unsigned long long g = bk;
#pragma unroll
        for (int o = 16; o; o >>= 1) {
            unsigned long long other = __shfl_xor_sync(0xffffffffu, g, o);
            g = min(g, other);
        }
        int jstar = (int)(g & 0xffffffffu);
        if (lane == 0) idx[n*KTOT + NLOC + s] = jstar;
        if ((jstar & 31) == lane) {
            removed |= 1u << (jstar >> 5);
            bk = 0xFFFFFFFFFFFFFFFFull;
#pragma unroll
            for (int t = 0; t < 32; t++) {
                if (removed & (1u << t)) continue;
                int j = lane + (t << 5);
                float d0 = x0 - xs0[j], d1 = x1 - xs1[j], d2 = x2 - xs2[j];
                float dd = d0*d0 + d1*d1 + d2*d2;
                unsigned long long k = ((unsigned long long)__float_as_uint(dd) << 32) | (unsigned)j;
                bk = min(bk, k);
            }
        }
    }
}

// ---------------------------------------------------------------------------
// Gather pair reps + LayerNorm (affine folded into Wb later).
// ---------------------------------------------------------------------------
__global__ void zn_kernel(const float* __restrict__ Z, const int* __restrict__ idx,
                          float* __restrict__ zn) {
    int e = blockIdx.x * blockDim.x + threadIdx.x;
    if (e >= N_TOK*KTOT) return;
    int n = e / KTOT;
    int j = idx[e];
    const float* z = Z + ((size_t)n * N_TOK + j) * CP;
    float m = 0.f;
#pragma unroll
    for (int c = 0; c < CP; c++) m += z[c];
    m *= (1.0f/CP);
    float v = 0.f;
#pragma unroll
    for (int c = 0; c < CP; c++) { float d = z[c]-m; v += d*d; }
    v *= (1.0f/CP);
    float r = rsqrtf(v + 1e-5f);
#pragma unroll
    for (int c = 0; c < CP; c++) zn[(size_t)e*CP + c] = (z[c]-m)*r;
}

// ---------------------------------------------------------------------------
// Row LayerNorm.
// ---------------------------------------------------------------------------
__global__ void ln_kernel(const float* __restrict__ X, const float* __restrict__ gamma,
                          float* __restrict__ Y, int W) {
    int n = blockIdx.x;
    int tid = threadIdx.x;
    const float* x = X + (size_t)n * W;
    int cnt = W >> 7;   // 3 or 6
    float v[6];
    float s = 0.f, s2 = 0.f;
    for (int i = 0; i < cnt; i++) {
        float t = x[tid + (i << 7)];
        v[i] = t; s += t; s2 += t*t;
    }
#pragma unroll
    for (int o = 16; o; o >>= 1) {
        s  += __shfl_xor_sync(0xffffffffu, s,  o);
        s2 += __shfl_xor_sync(0xffffffffu, s2, o);
    }
    __shared__ float ss[4], ss2[4];
    if ((tid & 31) == 0) { ss[tid >> 5] = s; ss2[tid >> 5] = s2; }
    __syncthreads();
    s  = ss[0]  + ss[1]  + ss[2]  + ss[3];
    s2 = ss2[0] + ss2[1] + ss2[2] + ss2[3];
    float m = s / W;
    float var = s2 / W - m*m;
    float r = rsqrtf(var + 1e-5f);
    for (int i = 0; i < cnt; i++) {
        int c = tid + (i << 7);
        float g = gamma ? gamma[c] : 1.0f;
        Y[(size_t)n*W + c] = (v[i]-m)*r*g;
    }
}

// ---------------------------------------------------------------------------
// Fold pair LN affine into Wb.
// ---------------------------------------------------------------------------
__global__ void fold_wb_kernel(const float* __restrict__ g, const float* __restrict__ b,
                               const float* __restrict__ Wb,
                               float* __restrict__ wbf, float* __restrict__ b0) {
    int t = threadIdx.x;
    if (t < CP*NH) {
        int c = t / NH;
        wbf[t] = g[c] * Wb[t];
    }
    if (t < NH) {
        float s = 0.f;
#pragma unroll
        for (int c = 0; c < CP; c++) s += b[c] * Wb[c*NH + t];
        b0[t] = s;
    }
}

// ---------------------------------------------------------------------------
// bf16 tensor-core GEMM, 64x64x32 tiles, double-buffered static smem with
// register prefetch: LDG(next) -> MMA(cur) -> cvt+STS(next) -> 1 barrier.
// Fragments via ldmatrix (A) / ldmatrix.trans (B); mma m16n8k16, fp32 accum.
// 8 warps (2x4), warp tile 32x16.
// MODE 0: C = acc1 + bias[c]                                (bias nullable)
// MODE 1: C = sigmoid(acc1+bias[c]) * extra + acc2           (adaLN dual)
// MODE 2: C += sigmoid(acc1+bias[c]) * extra                 (skip gate-add)
// MODE 3: C = silu(acc1) * acc2                              (SwiGLU dual)
// ---------------------------------------------------------------------------
#define BM 64
#define BN 64
#define BK 32
#define ASTRIDE 40   // BK + 8 halves -> 80B row stride (5x16B, conflict-free ldmatrix)
#define BSTRIDE 72   // BN + 8 halves -> 144B row stride (9x16B, conflict-free ldmatrix)

template<int MODE>
__device__ __forceinline__ void gemm_body(
        const float* __restrict__ A, const float* __restrict__ B1,
        const float* __restrict__ B2, const float* __restrict__ bias,
        const float* __restrict__ extra, float* __restrict__ C,
        int M, int N, int K) {
    constexpr bool DUAL = (MODE == 1 || MODE == 3);
    __shared__ unsigned short As [2][BM][ASTRIDE];
    __shared__ unsigned short Bs [2][BK][BSTRIDE];
    __shared__ unsigned short Bs2[DUAL ? 2 : 1][DUAL ? BK : 1][BSTRIDE];

    int tid = threadIdx.x;
    int lane = tid & 31, warp = tid >> 5;
    int wm = warp >> 2, wn = warp & 3;                // 2 x 4 warp grid
    int lr = lane >> 2, lc = lane & 3;
    int row0 = blockIdx.y * BM, col0 = blockIdx.x * BN;

    // ldg mapping: A 64 rows x 32 k -> thread = (row, 8-float chunk)
    int arow = tid >> 2, ac = (tid & 3) << 3;
    // B 32 k-rows x 64 n -> thread = (k-row, 8-float chunk)
    int brow = tid >> 3, bc = (tid & 7) << 3;

    const float* Ag  = A  + (size_t)(row0 + arow)*K + ac;
    const float* B1g = B1 + (size_t)brow*N + col0 + bc;
    const float* B2g = DUAL ? (B2 + (size_t)brow*N + col0 + bc) : nullptr;

    float4 ra0, ra1, rb0, rb1, rc0, rc1;

    auto ldg = [&](int k0) {
        ra0 = *(const float4*)(Ag + k0);
        ra1 = *(const float4*)(Ag + k0 + 4);
        rb0 = *(const float4*)(B1g + (size_t)k0*N);
        rb1 = *(const float4*)(B1g + (size_t)k0*N + 4);
        if (DUAL) {
            rc0 = *(const float4*)(B2g + (size_t)k0*N);
            rc1 = *(const float4*)(B2g + (size_t)k0*N + 4);
        }
    };
    auto sts = [&](int s) {
        *(uint4*)&As[s][arow][ac] = make_uint4(pk2bf(ra0.x, ra0.y), pk2bf(ra0.z, ra0.w),
                                               pk2bf(ra1.x, ra1.y), pk2bf(ra1.z, ra1.w));
        *(uint4*)&Bs[s][brow][bc] = make_uint4(pk2bf(rb0.x, rb0.y), pk2bf(rb0.z, rb0.w),
                                               pk2bf(rb1.x, rb1.y), pk2bf(rb1.z, rb1.w));
        if (DUAL) {
            *(uint4*)&Bs2[s][brow][bc] = make_uint4(pk2bf(rc0.x, rc0.y), pk2bf(rc0.z, rc0.w),
                                                    pk2bf(rc1.x, rc1.y), pk2bf(rc1.z, rc1.w));
        }
    };

    float acc [2][2][4] = {};
    float acc2[2][2][4] = {};

    // ldmatrix address precompute (lane-dependent, slab-invariant offsets)
    int lm  = lane >> 3;         // which 8x8 matrix this lane feeds
    int lr8 = lane & 7;          // row within matrix
    int a_row_off = (lm & 1)*8 + lr8;     // + mr
    int a_col_off = (lm >> 1)*8;          // + ks
    int b_k_off   = (lm & 1)*8 + lr8;     // + ks
    int b_n_off   = wn*16 + (lm >> 1)*8;

    int NIT = K / BK;
    ldg(0);
    sts(0);
    __syncthreads();

    for (int it = 0; it < NIT; it++) {
        int s = it & 1;
        if (it + 1 < NIT) ldg((it + 1) * BK);

#pragma unroll
        for (int ks = 0; ks < BK; ks += 16) {
            unsigned a[2][4], b[4], b2[4];
#pragma unroll
            for (int mi = 0; mi < 2; mi++) {
                int mr = wm*32 + mi*16;
                ldsm4(a[mi][0], a[mi][1], a[mi][2], a[mi][3],
                      sptr(&As[s][mr + a_row_off][ks + a_col_off]));
            }
            ldsm4t(b[0], b[1], b[2], b[3], sptr(&Bs[s][ks + b_k_off][b_n_off]));
            if (DUAL)
                ldsm4t(b2[0], b2[1], b2[2], b2[3], sptr(&Bs2[s][ks + b_k_off][b_n_off]));
#pragma unroll
            for (int mi = 0; mi < 2; mi++) {
                mma_bf16(acc[mi][0], a[mi], b[0], b[1]);
                mma_bf16(acc[mi][1], a[mi], b[2], b[3]);
                if (DUAL) {
                    mma_bf16(acc2[mi][0], a[mi], b2[0], b2[1]);
                    mma_bf16(acc2[mi][1], a[mi], b2[2], b2[3]);
                }
            }
        }

        if (it + 1 < NIT) sts((it + 1) & 1);
        __syncthreads();
    }

#pragma unroll
    for (int mi = 0; mi < 2; mi++) {
#pragma unroll
        for (int half = 0; half < 2; half++) {
            int r = row0 + wm*32 + mi*16 + lr + half*8;
#pragma unroll
            for (int ni = 0; ni < 2; ni++) {
                int cidx = col0 + wn*16 + ni*8 + 2*lc;
                size_t off = (size_t)r*N + cidx;
                float v0 = acc[mi][ni][half*2+0];
                float v1 = acc[mi][ni][half*2+1];
                float2 out;
                if (MODE == 0) {
                    float b0v = bias ? bias[cidx]   : 0.0f;
                    float b1v = bias ? bias[cidx+1] : 0.0f;
                    out.x = v0 + b0v; out.y = v1 + b1v;
                    *(float2*)(C + off) = out;
                } else if (MODE == 1) {
                    float2 ex = *(const float2*)(extra + off);
                    out.x = sigmoidf_(v0 + bias[cidx  ]) * ex.x + acc2[mi][ni][half*2+0];
                    out.y = sigmoidf_(v1 + bias[cidx+1]) * ex.y + acc2[mi][ni][half*2+1];
                    *(float2*)(C + off) = out;
                } else if (MODE == 2) {
                    float2 ex = *(const float2*)(extra + off);
                    float2 cv = *(const float2*)(C + off);
                    cv.x += sigmoidf_(v0 + bias[cidx  ]) * ex.x;
                    cv.y += sigmoidf_(v1 + bias[cidx+1]) * ex.y;
                    *(float2*)(C + off) = cv;
                } else { // MODE 3
                    out.x = v0 * sigmoidf_(v0) * acc2[mi][ni][half*2+0];
                    out.y = v1 * sigmoidf_(v1) * acc2[mi][ni][half*2+1];
                    *(float2*)(C + off) = out;
                }
            }
        }
    }
}

template<int MODE>
__global__ __launch_bounds__(256) void gemm_kernel(
        const float* __restrict__ A, const float* __restrict__ B1,
        const float* __restrict__ B2, const float* __restrict__ bias,
        const float* __restrict__ extra, float* __restrict__ C,
        int M, int N, int K) {
    gemm_body<MODE>(A, B1, B2, bias, extra, C, M, N, K);
}

// 4 MODE-0 GEMMs (same A) in one launch, selected by blockIdx.z.
struct QuadParams {
    const float* B[4];
    const float* bias[4];
    float* C[4];
};

__global__ __launch_bounds__(256) void gemm_quad_kernel(
        const float* __restrict__ A, QuadParams p, int M, int N, int K) {
    int z = blockIdx.z;
    gemm_body<0>(A, p.B[z], nullptr, p.bias[z], nullptr, p.C[z], M, N, K);
}

// ---------------------------------------------------------------------------
// Attention: per-token block. 16 heads x 40 keys, pair bias, softmax,
// weighted V sum, per-channel sigmoid gate (gpre).
// ---------------------------------------------------------------------------
__global__ void attn_kernel(const float* __restrict__ q, const float* __restrict__ kb,
                            const float* __restrict__ vb, const float* __restrict__ gpre,
                            const int* __restrict__ idx, const float* __restrict__ zn,
                            const float* __restrict__ wbf, const float* __restrict__ b0,
                            float* __restrict__ out) {
    const float SCALE = 0.14433756729740643f; // 1/sqrt(48)
    int n = blockIdx.x;
    int tid = threadIdx.x;
    __shared__ float qs[CT];
    __shared__ float zs[KTOT*CP];
    __shared__ int   js[KTOT];
    __shared__ float sc[NH*KTOT];

    for (int c = tid; c < CT; c += 256) qs[c] = q[(size_t)n*CT + c];
    if (tid < KTOT) js[tid] = idx[n*KTOT + tid];
    for (int c = tid; c < KTOT*CP; c += 256) zs[c] = zn[(size_t)n*KTOT*CP + c];
    __syncthreads();

    for (int e = tid; e < NH*KTOT; e += 256) {
        int h = e / KTOT, k = e % KTOT;
        int j = js[k];
        const float* kp = kb + (size_t)j*CT + h*DH;
        const float* qp = qs + h*DH;
        float s = 0.f;
#pragma unroll
        for (int d = 0; d < DH; d++) s += qp[d]*kp[d];
        s *= SCALE;
        float bb = b0[h];
        const float* zp = zs + k*CP;
#pragma unroll
        for (int c = 0; c < CP; c++) bb += zp[c]*wbf[c*NH + h];
        sc[e] = s + bb;
    }
    __syncthreads();

    if (tid < NH) {
        int h = tid;
        float mx = -FLT_MAX;
        for (int k = 0; k < KTOT; k++) mx = fmaxf(mx, sc[h*KTOT + k]);
        float sum = 0.f;
        for (int k = 0; k < KTOT; k++) {
            float ex = expf(sc[h*KTOT + k] - mx);
            sc[h*KTOT + k] = ex; sum += ex;
        }
        float inv = 1.0f / sum;
        for (int k = 0; k < KTOT; k++) sc[h*KTOT + k] *= inv;
    }
    __syncthreads();

    for (int c = tid; c < CT; c += 256) {
        int h = c / DH;
        float acc = 0.f;
#pragma unroll 8
        for (int k = 0; k < KTOT; k++)
            acc += sc[h*KTOT + k] * vb[(size_t)js[k]*CT + c];
        float g = gpre[(size_t)n*CT + c];
        out[(size_t)n*CT + c] = acc * sigmoidf_(g);
    }
}

// ---------------------------------------------------------------------------
extern "C" void kernel_launch(void* const* d_in, const int* in_sizes, int n_in,
                              void* d_out, int out_size) {
    const float* A_I      = (const float*)d_in[0];
    const float* S        = (const float*)d_in[1];
    const float* Z        = (const float*)d_in[2];
    const float* X_L      = (const float*)d_in[3];
    const float* aln1_g   = (const float*)d_in[5];
    const float* aln1_sw  = (const float*)d_in[6];
    const float* aln1_sb  = (const float*)d_in[7];
    const float* aln1_shw = (const float*)d_in[8];
    const float* Wq       = (const float*)d_in[9];
    const float* bq       = (const float*)d_in[10];
    const float* Wk       = (const float*)d_in[11];
    const float* Wv       = (const float*)d_in[12];
    const float* plg      = (const float*)d_in[13];
    const float* plb      = (const float*)d_in[14];
    const float* Wb       = (const float*)d_in[15];
    const float* Wg       = (const float*)d_in[16];
    const float* Wo       = (const float*)d_in[17];
    const float* sgw      = (const float*)d_in[18];
    const float* sgb      = (const float*)d_in[19];
    const float* aln2_g   = (const float*)d_in[20];
    const float* aln2_sw  = (const float*)d_in[21];
    const float* aln2_sb  = (const float*)d_in[22];
    const float* aln2_shw = (const float*)d_in[23];
    const float* tw1      = (const float*)d_in[24];
    const float* tw2      = (const float*)d_in[25];
    const float* tw3      = (const float*)d_in[26];
    const float* tsgw     = (const float*)d_in[27];
    const float* tsgb     = (const float*)d_in[28];

    float* A = (float*)d_out;

    float *sn, *normA, *an, *q, *kb, *vb, *gpre, *otmp, *ptmp, *hb, *zn, *wbf, *b0;
    int* idx;
    cudaGetSymbolAddress((void**)&sn,    g_sn);
    cudaGetSymbolAddress((void**)&normA, g_normA);
    cudaGetSymbolAddress((void**)&an,    g_an);
    cudaGetSymbolAddress((void**)&q,     g_q);
    cudaGetSymbolAddress((void**)&kb,    g_kb);
    cudaGetSymbolAddress((void**)&vb,    g_vb);
    cudaGetSymbolAddress((void**)&gpre,  g_gpre);
    cudaGetSymbolAddress((void**)&otmp,  g_otmp);
    cudaGetSymbolAddress((void**)&ptmp,  g_ptmp);
    cudaGetSymbolAddress((void**)&hb,    g_hb);
    cudaGetSymbolAddress((void**)&zn,    g_zn);
    cudaGetSymbolAddress((void**)&wbf,   g_wbf);
    cudaGetSymbolAddress((void**)&b0,    g_b0);
    cudaGetSymbolAddress((void**)&idx,   g_idx);

    cudaMemcpyAsync(A, A_I, (size_t)N_TOK*CT*sizeof(float), cudaMemcpyDeviceToDevice, 0);

    idx_kernel<<<N_TOK/8, 256>>>(X_L, idx);
    zn_kernel<<<(N_TOK*KTOT + 255)/256, 256>>>(Z, idx, zn);

    dim3 g768(CT/BN, N_TOK/BM);
    dim3 g1536(2*CT/BN, N_TOK/BM);
    dim3 gq(CT/BN, N_TOK/BM, 4);

    for (int i = 0; i < NB; i++) {
        size_t wo_ct  = (size_t)i*CT*CT;
        size_t wo_cs  = (size_t)i*CS*CT;
        size_t wo_t12 = (size_t)i*CT*2*CT;
        size_t wo_t3  = (size_t)i*2*CT*CT;

        // --- LocalAttentionPairBias ---
        ln_kernel<<<N_TOK, 128>>>(S, aln1_g + i*CS, sn, CS);
        ln_kernel<<<N_TOK, 128>>>(A, nullptr, normA, CT);
        gemm_kernel<1><<<g768, 256>>>(sn, aln1_sw + wo_cs, aln1_shw + wo_cs,
                                      aln1_sb + i*CT, normA, an, N_TOK, CT, CS);
        QuadParams qp;
        qp.B[0] = Wq + wo_ct; qp.bias[0] = bq + i*CT; qp.C[0] = q;
        qp.B[1] = Wk + wo_ct; qp.bias[1] = nullptr;   qp.C[1] = kb;
        qp.B[2] = Wv + wo_ct; qp.bias[2] = nullptr;   qp.C[2] = vb;
        qp.B[3] = Wg + wo_ct; qp.bias[3] = nullptr;   qp.C[3] = gpre;
        gemm_quad_kernel<<<gq, 256>>>(an, qp, N_TOK, CT, CT);
        fold_wb_kernel<<<1, 256>>>(plg + i*CP, plb + i*CP, Wb + i*CP*NH, wbf, b0);
        attn_kernel<<<N_TOK, 256>>>(q, kb, vb, gpre, idx, zn, wbf, b0, otmp);
        gemm_kernel<0><<<g768, 256>>>(otmp, Wo + wo_ct, nullptr, nullptr, nullptr, ptmp, N_TOK, CT, CT);
        gemm_kernel<2><<<g768, 256>>>(S, sgw + wo_cs, nullptr, sgb + i*CT, ptmp, A, N_TOK, CT, CS);

        // --- ConditionedTransitionBlock ---
        ln_kernel<<<N_TOK, 128>>>(S, aln2_g + i*CS, sn, CS);
        ln_kernel<<<N_TOK, 128>>>(A, nullptr, normA, CT);
        gemm_kernel<1><<<g768, 256>>>(sn, aln2_sw + wo_cs, aln2_shw + wo_cs,
                                      aln2_sb + i*CT, normA, an, N_TOK, CT, CS);
        gemm_kernel<3><<<g1536, 256>>>(an, tw1 + wo_t12, tw2 + wo_t12, nullptr, nullptr,
                                       hb, N_TOK, 2*CT, CT);
        gemm_kernel<0><<<g768, 256>>>(hb, tw3 + wo_t3, nullptr, nullptr, nullptr, ptmp, N_TOK, CT, 2*CT);
        gemm_kernel<2><<<g768, 256>>>(S, tsgw + wo_cs, nullptr, tsgb + i*CT, ptmp, A, N_TOK, CT, CS);
    }
}

// round 10
// speedup vs baseline: 5.4314x; 1.2881x over previous
#include <cuda_runtime.h>
#include <cuda_bf16.h>
#include <math.h>
#include <float.h>

#define N_TOK 1024
#define CT    768
#define CS    384
#define CP    16
#define NH    16
#define DH    48
#define NB    4
#define NLOC  8
#define NKNN  32
#define KTOT  40

typedef __nv_bfloat16 bf16;
typedef __nv_bfloat162 bf162;

// fp32 scratch
static __device__ float g_normA[N_TOK*CT];
static __device__ float g_q    [N_TOK*CT];
static __device__ float g_kb   [N_TOK*CT];
static __device__ float g_vb   [N_TOK*CT];
static __device__ float g_gpre [N_TOK*CT];
static __device__ float g_ptmp [N_TOK*CT];
static __device__ float g_zn   [N_TOK*KTOT*CP];
static __device__ int   g_idx  [N_TOK*KTOT];
static __device__ float g_wbf  [CP*NH];
static __device__ float g_b0   [NH];

// bf16 activations
static __device__ bf16 g_sn_bf  [N_TOK*CS];
static __device__ bf16 g_S_bf   [N_TOK*CS];
static __device__ bf16 g_an_bf  [N_TOK*CT];
static __device__ bf16 g_otmp_bf[N_TOK*CT];
static __device__ bf16 g_hb_bf  [N_TOK*2*CT];

// bf16 pre-converted weights
static __device__ bf16 g_w_a1sw [NB*CS*CT];
static __device__ bf16 g_w_a1shw[NB*CS*CT];
static __device__ bf16 g_w_q    [NB*CT*CT];
static __device__ bf16 g_w_k    [NB*CT*CT];
static __device__ bf16 g_w_v    [NB*CT*CT];
static __device__ bf16 g_w_g    [NB*CT*CT];
static __device__ bf16 g_w_o    [NB*CT*CT];
static __device__ bf16 g_w_sg   [NB*CS*CT];
static __device__ bf16 g_w_a2sw [NB*CS*CT];
static __device__ bf16 g_w_a2shw[NB*CS*CT];
static __device__ bf16 g_w_t1   [NB*CT*2*CT];
static __device__ bf16 g_w_t2   [NB*CT*2*CT];
static __device__ bf16 g_w_t3   [NB*2*CT*CT];
static __device__ bf16 g_w_tsg  [NB*CS*CT];

__device__ __forceinline__ float sigmoidf_(float x) { return 1.0f / (1.0f + expf(-x)); }

__device__ __forceinline__ unsigned sptr(const void* p) {
    return (unsigned)__cvta_generic_to_shared(p);
}

__device__ __forceinline__ void cpasync16(unsigned dst, const void* src) {
    asm volatile("cp.async.cg.shared.global [%0],[%1],16;" :: "r"(dst), "l"(src));
}
#define CP_COMMIT() asm volatile("cp.async.commit_group;")
#define CP_WAIT1()  asm volatile("cp.async.wait_group 1;")

__device__ __forceinline__ void ldsm4(unsigned& r0, unsigned& r1, unsigned& r2, unsigned& r3,
                                      unsigned addr) {
    asm volatile("ldmatrix.sync.aligned.m8n8.x4.shared.b16 {%0,%1,%2,%3},[%4];"
                 : "=r"(r0), "=r"(r1), "=r"(r2), "=r"(r3) : "r"(addr));
}

__device__ __forceinline__ void ldsm4t(unsigned& r0, unsigned& r1, unsigned& r2, unsigned& r3,
                                       unsigned addr) {
    asm volatile("ldmatrix.sync.aligned.m8n8.x4.trans.shared.b16 {%0,%1,%2,%3},[%4];"
                 : "=r"(r0), "=r"(r1), "=r"(r2), "=r"(r3) : "r"(addr));
}

__device__ __forceinline__ void mma_bf16(float* c, const unsigned* a, unsigned b0, unsigned b1) {
    asm volatile(
        "mma.sync.aligned.m16n8k16.row.col.f32.bf16.bf16.f32 "
        "{%0,%1,%2,%3},{%4,%5,%6,%7},{%8,%9},{%0,%1,%2,%3};\n"
        : "+f"(c[0]), "+f"(c[1]), "+f"(c[2]), "+f"(c[3])
        : "r"(a[0]), "r"(a[1]), "r"(a[2]), "r"(a[3]), "r"(b0), "r"(b1));
}

// ---------------------------------------------------------------------------
// fp32 -> bf16 bulk convert (weights + S), 15 tensors in one launch.
// ---------------------------------------------------------------------------
struct CvtEnt { const float* s; bf16* d; int n; };
struct CvtList { CvtEnt e[15]; };

__global__ void cvt_kernel(CvtList L) {
    CvtEnt c = L.e[blockIdx.y];
    int stride = gridDim.x * blockDim.x;
    for (int i = blockIdx.x*blockDim.x + threadIdx.x; i*4 < c.n; i += stride) {
        float4 v = *(const float4*)(c.s + i*4);
        *(bf162*)(c.d + i*4)     = __floats2bfloat162_rn(v.x, v.y);
        *(bf162*)(c.d + i*4 + 2) = __floats2bfloat162_rn(v.z, v.w);
    }
}

// ---------------------------------------------------------------------------
// kNN indices: warp-per-token iterative extract-min with (dist,idx) packed keys.
// ---------------------------------------------------------------------------
__global__ void idx_kernel(const float* __restrict__ X, int* __restrict__ idx) {
    __shared__ float xs0[N_TOK], xs1[N_TOK], xs2[N_TOK];
    int tid = threadIdx.x;
    for (int j = tid; j < N_TOK; j += 256) {
        xs0[j] = X[j*3+0]; xs1[j] = X[j*3+1]; xs2[j] = X[j*3+2];
    }
    __syncthreads();
    int lane = tid & 31, warp = tid >> 5;
    int n = blockIdx.x*8 + warp;
    if (lane < NLOC) {
        int v = n - NLOC/2 + lane;
        idx[n*KTOT + lane] = min(max(v, 0), N_TOK-1);
    }
    float x0 = xs0[n], x1 = xs1[n], x2 = xs2[n];

    unsigned removed = 0;
    unsigned long long bk = 0xFFFFFFFFFFFFFFFFull;
#pragma unroll
    for (int t = 0; t < 32; t++) {
        int j = lane + (t << 5);
        float d0 = x0 - xs0[j], d1 = x1 - xs1[j], d2 = x2 - xs2[j];
        float dd = d0*d0 + d1*d1 + d2*d2;
        unsigned long long k = ((unsigned long long)__float_as_uint(dd) << 32) | (unsigned)j;
        bk = min(bk, k);
    }
    for (int s = 0; s < NKNN; s++) {
        unsigned long long g = bk;
#pragma unroll
        for (int o = 16; o; o >>= 1) {
            unsigned long long other = __shfl_xor_sync(0xffffffffu, g, o);
            g = min(g, other);
        }
        int jstar = (int)(g & 0xffffffffu);
        if (lane == 0) idx[n*KTOT + NLOC + s] = jstar;
        if ((jstar & 31) == lane) {
            removed |= 1u << (jstar >> 5);
            bk = 0xFFFFFFFFFFFFFFFFull;
#pragma unroll
            for (int t = 0; t < 32; t++) {
                if (removed & (1u << t)) continue;
                int j = lane + (t << 5);
                float d0 = x0 - xs0[j], d1 = x1 - xs1[j], d2 = x2 - xs2[j];
                float dd = d0*d0 + d1*d1 + d2*d2;
                unsigned long long k = ((unsigned long long)__float_as_uint(dd) << 32) | (unsigned)j;
                bk = min(bk, k);
            }
        }
    }
}

// ---------------------------------------------------------------------------
// Gather pair reps + LayerNorm (affine folded into Wb later).
// ---------------------------------------------------------------------------
__global__ void zn_kernel(const float* __restrict__ Z, const int* __restrict__ idx,
                          float* __restrict__ zn) {
    int e = blockIdx.x * blockDim.x + threadIdx.x;
    if (e >= N_TOK*KTOT) return;
    int n = e / KTOT;
    int j = idx[e];
    const float* z = Z + ((size_t)n * N_TOK + j) * CP;
    float m = 0.f;
#pragma unroll
    for (int c = 0; c < CP; c++) m += z[c];
    m *= (1.0f/CP);
    float v = 0.f;
#pragma unroll
    for (int c = 0; c < CP; c++) { float d = z[c]-m; v += d*d; }
    v *= (1.0f/CP);
    float r = rsqrtf(v + 1e-5f);
#pragma unroll
    for (int c = 0; c < CP; c++) zn[(size_t)e*CP + c] = (z[c]-m)*r;
}

// ---------------------------------------------------------------------------
// Row LayerNorm; writes bf16 (if Ybf) or fp32 (Y).
// ---------------------------------------------------------------------------
__global__ void ln_kernel(const float* __restrict__ X, const float* __restrict__ gamma,
                          float* __restrict__ Y, bf16* __restrict__ Ybf, int W) {
    int n = blockIdx.x;
    int tid = threadIdx.x;
    const float* x = X + (size_t)n * W;
    int cnt = W >> 7;   // 3 or 6
    float v[6];
    float s = 0.f, s2 = 0.f;
    for (int i = 0; i < cnt; i++) {
        float t = x[tid + (i << 7)];
        v[i] = t; s += t; s2 += t*t;
    }
#pragma unroll
    for (int o = 16; o; o >>= 1) {
        s  += __shfl_xor_sync(0xffffffffu, s,  o);
        s2 += __shfl_xor_sync(0xffffffffu, s2, o);
    }
    __shared__ float ss[4], ss2[4];
    if ((tid & 31) == 0) { ss[tid >> 5] = s; ss2[tid >> 5] = s2; }
    __syncthreads();
    s  = ss[0]  + ss[1]  + ss[2]  + ss[3];
    s2 = ss2[0] + ss2[1] + ss2[2] + ss2[3];
    float m = s / W;
    float var = s2 / W - m*m;
    float r = rsqrtf(var + 1e-5f);
    for (int i = 0; i < cnt; i++) {
        int c = tid + (i << 7);
        float g = gamma ? gamma[c] : 1.0f;
        float o = (v[i]-m)*r*g;
        if (Ybf) Ybf[(size_t)n*W + c] = __float2bfloat16(o);
        else     Y  [(size_t)n*W + c] = o;
    }
}

// ---------------------------------------------------------------------------
// Fold pair LN affine into Wb.
// ---------------------------------------------------------------------------
__global__ void fold_wb_kernel(const float* __restrict__ g, const float* __restrict__ b,
                               const float* __restrict__ Wb,
                               float* __restrict__ wbf, float* __restrict__ b0) {
    int t = threadIdx.x;
    if (t < CP*NH) {
        int c = t / NH;
        wbf[t] = g[c] * Wb[t];
    }
    if (t < NH) {
        float s = 0.f;
#pragma unroll
        for (int c = 0; c < CP; c++) s += b[c] * Wb[c*NH + t];
        b0[t] = s;
    }
}

// ---------------------------------------------------------------------------
// bf16 tensor-core GEMM, 64x64x32 tiles, 3-stage cp.async pipeline.
// A[M,K] bf16 row-major, B[K,N] bf16 row-major; ldmatrix fragments;
// mma m16n8k16, fp32 accum. 8 warps (2x4), warp tile 32x16.
// MODE 0: C = acc1 + bias[c]                                (bias nullable, fp32 out)
// MODE 1: C = sigmoid(acc1+bias[c]) * extra + acc2           (adaLN dual, bf16 out)
// MODE 2: C += sigmoid(acc1+bias[c]) * extra                 (skip gate-add, fp32 out)
// MODE 3: C = silu(acc1) * acc2                              (SwiGLU dual, bf16 out)
// ---------------------------------------------------------------------------
#define BM 64
#define BN 64
#define BK 32
#define STAGES 3
#define ASTRIDE 40   // BK + 8 halves -> 80B row stride (5x16B, conflict-free ldmatrix)
#define BSTRIDE 72   // BN + 8 halves -> 144B row stride (9x16B, conflict-free ldmatrix)

template<int MODE>
__device__ __forceinline__ void gemm_body(
        const bf16* __restrict__ A, const bf16* __restrict__ B1,
        const bf16* __restrict__ B2, const float* __restrict__ bias,
        const float* __restrict__ extra, void* __restrict__ Cp,
        int M, int N, int K) {
    constexpr bool DUAL  = (MODE == 1 || MODE == 3);
    constexpr bool OUTBF = (MODE == 1 || MODE == 3);
    __shared__ __align__(16) unsigned short As [STAGES][BM][ASTRIDE];
    __shared__ __align__(16) unsigned short Bs [STAGES][BK][BSTRIDE];
    __shared__ __align__(16) unsigned short Bs2[DUAL ? STAGES : 1][DUAL ? BK : 1][BSTRIDE];

    int tid = threadIdx.x;
    int lane = tid & 31, warp = tid >> 5;
    int wm = warp >> 2, wn = warp & 3;                // 2 x 4 warp grid
    int lr = lane >> 2, lc = lane & 3;
    int row0 = blockIdx.y * BM, col0 = blockIdx.x * BN;

    // cp.async mapping: A tile 64x32 bf16 -> 256 x 16B; B tile 32x64 -> 256 x 16B
    int arow = tid >> 2, ac = (tid & 3) << 3;
    int brow = tid >> 3, bc = (tid & 7) << 3;

    const bf16* Ag  = A  + (size_t)(row0 + arow)*K + ac;
    const bf16* B1g = B1 + (size_t)brow*N + col0 + bc;
    const bf16* B2g = DUAL ? (B2 + (size_t)brow*N + col0 + bc) : nullptr;

    auto issue = [&](int s, int k0) {
        cpasync16(sptr(&As[s][arow][ac]), Ag + k0);
        cpasync16(sptr(&Bs[s][brow][bc]), B1g + (size_t)k0*N);
        if (DUAL) cpasync16(sptr(&Bs2[s][brow][bc]), B2g + (size_t)k0*N);
    };

    float acc [2][2][4] = {};
    float acc2[2][2][4] = {};

    // ldmatrix lane offsets (slab-invariant)
    int lm  = lane >> 3;
    int lr8 = lane & 7;
    int a_row_off = (lm & 1)*8 + lr8;
    int a_col_off = (lm >> 1)*8;
    int b_k_off   = (lm & 1)*8 + lr8;
    int b_n_off   = wn*16 + (lm >> 1)*8;

    int NIT = K / BK;          // >= 12 for all shapes
    issue(0, 0);       CP_COMMIT();
    issue(1, BK);      CP_COMMIT();

    for (int it = 0; it < NIT; it++) {
        CP_WAIT1();
        __syncthreads();
        int s = it % STAGES;

#pragma unroll
        for (int ks = 0; ks < BK; ks += 16) {
            unsigned a[2][4], b[4], b2[4];
#pragma unroll
            for (int mi = 0; mi < 2; mi++) {
                int mr = wm*32 + mi*16;
                ldsm4(a[mi][0], a[mi][1], a[mi][2], a[mi][3],
                      sptr(&As[s][mr + a_row_off][ks + a_col_off]));
            }
            ldsm4t(b[0], b[1], b[2], b[3], sptr(&Bs[s][ks + b_k_off][b_n_off]));
            if (DUAL)
                ldsm4t(b2[0], b2[1], b2[2], b2[3], sptr(&Bs2[s][ks + b_k_off][b_n_off]));
#pragma unroll
            for (int mi = 0; mi < 2; mi++) {
                mma_bf16(acc[mi][0], a[mi], b[0], b[1]);
                mma_bf16(acc[mi][1], a[mi], b[2], b[3]);
                if (DUAL) {
                    mma_bf16(acc2[mi][0], a[mi], b2[0], b2[1]);
                    mma_bf16(acc2[mi][1], a[mi], b2[2], b2[3]);
                }
            }
        }

        if (it + 2 < NIT) issue((it + 2) % STAGES, (it + 2) * BK);
        CP_COMMIT();
    }

    float* Cf = (float*)Cp;
    bf16*  Cb = (bf16*)Cp;

#pragma unroll
    for (int mi = 0; mi < 2; mi++) {
#pragma unroll
        for (int half = 0; half < 2; half++) {
            int r = row0 + wm*32 + mi*16 + lr + half*8;
#pragma unroll
            for (int ni = 0; ni < 2; ni++) {
                int cidx = col0 + wn*16 + ni*8 + 2*lc;
                size_t off = (size_t)r*N + cidx;
                float v0 = acc[mi][ni][half*2+0];
                float v1 = acc[mi][ni][half*2+1];
                if (MODE == 0) {
                    float b0v = bias ? bias[cidx]   : 0.0f;
                    float b1v = bias ? bias[cidx+1] : 0.0f;
                    float2 out; out.x = v0 + b0v; out.y = v1 + b1v;
                    *(float2*)(Cf + off) = out;
                } else if (MODE == 1) {
                    float2 ex = *(const float2*)(extra + off);
                    float ox = sigmoidf_(v0 + bias[cidx  ]) * ex.x + acc2[mi][ni][half*2+0];
                    float oy = sigmoidf_(v1 + bias[cidx+1]) * ex.y + acc2[mi][ni][half*2+1];
                    *(bf162*)(Cb + off) = __floats2bfloat162_rn(ox, oy);
                } else if (MODE == 2) {
                    float2 ex = *(const float2*)(extra + off);
                    float2 cv = *(const float2*)(Cf + off);
                    cv.x += sigmoidf_(v0 + bias[cidx  ]) * ex.x;
                    cv.y += sigmoidf_(v1 + bias[cidx+1]) * ex.y;
                    *(float2*)(Cf + off) = cv;
                } else { // MODE 3
                    float ox = v0 * sigmoidf_(v0) * acc2[mi][ni][half*2+0];
                    float oy = v1 * sigmoidf_(v1) * acc2[mi][ni][half*2+1];
                    *(bf162*)(Cb + off) = __floats2bfloat162_rn(ox, oy);
                }
            }
        }
    }
}

template<int MODE>
__global__ __launch_bounds__(256) void gemm_kernel(
        const bf16* __restrict__ A, const bf16* __restrict__ B1,
        const bf16* __restrict__ B2, const float* __restrict__ bias,
        const float* __restrict__ extra, void* __restrict__ C,
        int M, int N, int K) {
    gemm_body<MODE>(A, B1, B2, bias, extra, C, M, N, K);
}

// 4 MODE-0 GEMMs (same A) in one launch, selected by blockIdx.z.
struct QuadParams {
    const bf16* B[4];
    const float* bias[4];
    float* C[4];
};

__global__ __launch_bounds__(256) void gemm_quad_kernel(
        const bf16* __restrict__ A, QuadParams p, int M, int N, int K) {
    int z = blockIdx.z;
    gemm_body<0>(A, p.B[z], nullptr, p.bias[z], nullptr, p.C[z], M, N, K);
}

// ---------------------------------------------------------------------------
// Attention: per-token block. 16 heads x 40 keys, pair bias, softmax,
// weighted V sum, per-channel sigmoid gate (gpre). Writes bf16 (GEMM input).
// ---------------------------------------------------------------------------
__global__ void attn_kernel(const float* __restrict__ q, const float* __restrict__ kb,
                            const float* __restrict__ vb, const float* __restrict__ gpre,
                            const int* __restrict__ idx, const float* __restrict__ zn,
                            const float* __restrict__ wbf, const float* __restrict__ b0,
                            bf16* __restrict__ out) {
    const float SCALE = 0.14433756729740643f; // 1/sqrt(48)
    int n = blockIdx.x;
    int tid = threadIdx.x;
    __shared__ float qs[CT];
    __shared__ float zs[KTOT*CP];
    __shared__ int   js[KTOT];
    __shared__ float sc[NH*KTOT];

    for (int c = tid; c < CT; c += 256) qs[c] = q[(size_t)n*CT + c];
    if (tid < KTOT) js[tid] = idx[n*KTOT + tid];
    for (int c = tid; c < KTOT*CP; c += 256) zs[c] = zn[(size_t)n*KTOT*CP + c];
    __syncthreads();

    for (int e = tid; e < NH*KTOT; e += 256) {
        int h = e / KTOT, k = e % KTOT;
        int j = js[k];
        const float* kp = kb + (size_t)j*CT + h*DH;
        const float* qp = qs + h*DH;
        float s = 0.f;
#pragma unroll
        for (int d = 0; d < DH; d++) s += qp[d]*kp[d];
        s *= SCALE;
        float bb = b0[h];
        const float* zp = zs + k*CP;
#pragma unroll
        for (int c = 0; c < CP; c++) bb += zp[c]*wbf[c*NH + h];
        sc[e] = s + bb;
    }
    __syncthreads();

    if (tid < NH) {
        int h = tid;
        float mx = -FLT_MAX;
        for (int k = 0; k < KTOT; k++) mx = fmaxf(mx, sc[h*KTOT + k]);
        float sum = 0.f;
        for (int k = 0; k < KTOT; k++) {
            float ex = expf(sc[h*KTOT + k] - mx);
            sc[h*KTOT + k] = ex; sum += ex;
        }
        float inv = 1.0f / sum;
        for (int k = 0; k < KTOT; k++) sc[h*KTOT + k] *= inv;
    }
    __syncthreads();

    for (int c = tid; c < CT; c += 256) {
        int h = c / DH;
        float acc = 0.f;
#pragma unroll 8
        for (int k = 0; k < KTOT; k++)
            acc += sc[h*KTOT + k] * vb[(size_t)js[k]*CT + c];
        float g = gpre[(size_t)n*CT + c];
        out[(size_t)n*CT + c] = __float2bfloat16(acc * sigmoidf_(g));
    }
}

// ---------------------------------------------------------------------------
extern "C" void kernel_launch(void* const* d_in, const int* in_sizes, int n_in,
                              void* d_out, int out_size) {
    const float* A_I      = (const float*)d_in[0];
    const float* S        = (const float*)d_in[1];
    const float* Z        = (const float*)d_in[2];
    const float* X_L      = (const float*)d_in[3];
    const float* aln1_g   = (const float*)d_in[5];
    const float* aln1_sw  = (const float*)d_in[6];
    const float* aln1_sb  = (const float*)d_in[7];
    const float* aln1_shw = (const float*)d_in[8];
    const float* Wq       = (const float*)d_in[9];
    const float* bq       = (const float*)d_in[10];
    const float* Wk       = (const float*)d_in[11];
    const float* Wv       = (const float*)d_in[12];
    const float* plg      = (const float*)d_in[13];
    const float* plb      = (const float*)d_in[14];
    const float* Wb       = (const float*)d_in[15];
    const float* Wg       = (const float*)d_in[16];
    const float* Wo       = (const float*)d_in[17];
    const float* sgw      = (const float*)d_in[18];
    const float* sgb      = (const float*)d_in[19];
    const float* aln2_g   = (const float*)d_in[20];
    const float* aln2_sw  = (const float*)d_in[21];
    const float* aln2_sb  = (const float*)d_in[22];
    const float* aln2_shw = (const float*)d_in[23];
    const float* tw1      = (const float*)d_in[24];
    const float* tw2      = (const float*)d_in[25];
    const float* tw3      = (const float*)d_in[26];
    const float* tsgw     = (const float*)d_in[27];
    const float* tsgb     = (const float*)d_in[28];

    float* A = (float*)d_out;

    float *normA, *q, *kb, *vb, *gpre, *ptmp, *zn, *wbf, *b0;
    int* idx;
    bf16 *sn_bf, *S_bf, *an_bf, *otmp_bf, *hb_bf;
    bf16 *w_a1sw, *w_a1shw, *w_q, *w_k, *w_v, *w_g, *w_o, *w_sg;
    bf16 *w_a2sw, *w_a2shw, *w_t1, *w_t2, *w_t3, *w_tsg;

    cudaGetSymbolAddress((void**)&normA,   g_normA);
    cudaGetSymbolAddress((void**)&q,       g_q);
    cudaGetSymbolAddress((void**)&kb,      g_kb);
    cudaGetSymbolAddress((void**)&vb,      g_vb);
    cudaGetSymbolAddress((void**)&gpre,    g_gpre);
    cudaGetSymbolAddress((void**)&ptmp,    g_ptmp);
    cudaGetSymbolAddress((void**)&zn,      g_zn);
    cudaGetSymbolAddress((void**)&wbf,     g_wbf);
    cudaGetSymbolAddress((void**)&b0,      g_b0);
    cudaGetSymbolAddress((void**)&idx,     g_idx);
    cudaGetSymbolAddress((void**)&sn_bf,   g_sn_bf);
    cudaGetSymbolAddress((void**)&S_bf,    g_S_bf);
    cudaGetSymbolAddress((void**)&an_bf,   g_an_bf);
    cudaGetSymbolAddress((void**)&otmp_bf, g_otmp_bf);
    cudaGetSymbolAddress((void**)&hb_bf,   g_hb_bf);
    cudaGetSymbolAddress((void**)&w_a1sw,  g_w_a1sw);
    cudaGetSymbolAddress((void**)&w_a1shw, g_w_a1shw);
    cudaGetSymbolAddress((void**)&w_q,     g_w_q);
    cudaGetSymbolAddress((void**)&w_k,     g_w_k);
    cudaGetSymbolAddress((void**)&w_v,     g_w_v);
    cudaGetSymbolAddress((void**)&w_g,     g_w_g);
    cudaGetSymbolAddress((void**)&w_o,     g_w_o);
    cudaGetSymbolAddress((void**)&w_sg,    g_w_sg);
    cudaGetSymbolAddress((void**)&w_a2sw,  g_w_a2sw);
    cudaGetSymbolAddress((void**)&w_a2shw, g_w_a2shw);
    cudaGetSymbolAddress((void**)&w_t1,    g_w_t1);
    cudaGetSymbolAddress((void**)&w_t2,    g_w_t2);
    cudaGetSymbolAddress((void**)&w_t3,    g_w_t3);
    cudaGetSymbolAddress((void**)&w_tsg,   g_w_tsg);

    cudaMemcpyAsync(A, A_I, (size_t)N_TOK*CT*sizeof(float), cudaMemcpyDeviceToDevice, 0);

    // One-shot conversions (weights + S) to bf16
    CvtList cl;
    cl.e[0]  = { aln1_sw,  w_a1sw,  NB*CS*CT };
    cl.e[1]  = { aln1_shw, w_a1shw, NB*CS*CT };
    cl.e[2]  = { Wq,       w_q,     NB*CT*CT };
    cl.e[3]  = { Wk,       w_k,     NB*CT*CT };
    cl.e[4]  = { Wv,       w_v,     NB*CT*CT };
    cl.e[5]  = { Wg,       w_g,     NB*CT*CT };
    cl.e[6]  = { Wo,       w_o,     NB*CT*CT };
    cl.e[7]  = { sgw,      w_sg,    NB*CS*CT };
    cl.e[8]  = { aln2_sw,  w_a2sw,  NB*CS*CT };
    cl.e[9]  = { aln2_shw, w_a2shw, NB*CS*CT };
    cl.e[10] = { tw1,      w_t1,    NB*CT*2*CT };
    cl.e[11] = { tw2,      w_t2,    NB*CT*2*CT };
    cl.e[12] = { tw3,      w_t3,    NB*2*CT*CT };
    cl.e[13] = { tsgw,     w_tsg,   NB*CS*CT };
    cl.e[14] = { S,        S_bf,    N_TOK*CS };
    cvt_kernel<<<dim3(128, 15), 256>>>(cl);

    idx_kernel<<<N_TOK/8, 256>>>(X_L, idx);
    zn_kernel<<<(N_TOK*KTOT + 255)/256, 256>>>(Z, idx, zn);

    dim3 g768(CT/BN, N_TOK/BM);
    dim3 g1536(2*CT/BN, N_TOK/BM);
    dim3 gq(CT/BN, N_TOK/BM, 4);

    for (int i = 0; i < NB; i++) {
        size_t wo_ct  = (size_t)i*CT*CT;
        size_t wo_cs  = (size_t)i*CS*CT;
        size_t wo_t12 = (size_t)i*CT*2*CT;
        size_t wo_t3  = (size_t)i*2*CT*CT;

        // --- LocalAttentionPairBias ---
        ln_kernel<<<N_TOK, 128>>>(S, aln1_g + i*CS, nullptr, sn_bf, CS);
        ln_kernel<<<N_TOK, 128>>>(A, nullptr, normA, nullptr, CT);
        gemm_kernel<1><<<g768, 256>>>(sn_bf, w_a1sw + wo_cs, w_a1shw + wo_cs,
                                      aln1_sb + i*CT, normA, an_bf, N_TOK, CT, CS);
        QuadParams qp;
        qp.B[0] = w_q + wo_ct; qp.bias[0] = bq + i*CT; qp.C[0] = q;
        qp.B[1] = w_k + wo_ct; qp.bias[1] = nullptr;   qp.C[1] = kb;
        qp.B[2] = w_v + wo_ct; qp.bias[2] = nullptr;   qp.C[2] = vb;
        qp.B[3] = w_g + wo_ct; qp.bias[3] = nullptr;   qp.C[3] = gpre;
        gemm_quad_kernel<<<gq, 256>>>(an_bf, qp, N_TOK, CT, CT);
        fold_wb_kernel<<<1, 256>>>(plg + i*CP, plb + i*CP, Wb + i*CP*NH, wbf, b0);
        attn_kernel<<<N_TOK, 256>>>(q, kb, vb, gpre, idx, zn, wbf, b0, otmp_bf);
        gemm_kernel<0><<<g768, 256>>>(otmp_bf, w_o + wo_ct, nullptr, nullptr, nullptr,
                                      ptmp, N_TOK, CT, CT);
        gemm_kernel<2><<<g768, 256>>>(S_bf, w_sg + wo_cs, nullptr, sgb + i*CT, ptmp,
                                      A, N_TOK, CT, CS);

        // --- ConditionedTransitionBlock ---
        ln_kernel<<<N_TOK, 128>>>(S, aln2_g + i*CS, nullptr, sn_bf, CS);
        ln_kernel<<<N_TOK, 128>>>(A, nullptr, normA, nullptr, CT);
        gemm_kernel<1><<<g768, 256>>>(sn_bf, w_a2sw + wo_cs, w_a2shw + wo_cs,
                                      aln2_sb + i*CT, normA, an_bf, N_TOK, CT, CS);
        gemm_kernel<3><<<g1536, 256>>>(an_bf, w_t1 + wo_t12, w_t2 + wo_t12, nullptr, nullptr,
                                       hb_bf, N_TOK, 2*CT, CT);
        gemm_kernel<0><<<g768, 256>>>(hb_bf, w_t3 + wo_t3, nullptr, nullptr, nullptr,
                                      ptmp, N_TOK, CT, 2*CT);
        gemm_kernel<2><<<g768, 256>>>(S_bf, w_tsg + wo_cs, nullptr, tsgb + i*CT, ptmp,
                                      A, N_TOK, CT, CS);
    }
}

// round 11
// speedup vs baseline: 5.6595x; 1.0420x over previous
#include <cuda_runtime.h>
#include <cuda_bf16.h>
#include <math.h>
#include <float.h>

#define N_TOK 1024
#define CT    768
#define CS    384
#define CP    16
#define NH    16
#define DH    48
#define NB    4
#define NLOC  8
#define NKNN  32
#define KTOT  40

typedef __nv_bfloat16 bf16;
typedef __nv_bfloat162 bf162;

// fp32 scratch
static __device__ float g_normA[N_TOK*CT];
static __device__ float g_q    [N_TOK*CT];
static __device__ float g_kb   [N_TOK*CT];
static __device__ float g_vb   [N_TOK*CT];
static __device__ float g_gpre [N_TOK*CT];
static __device__ float g_zn   [N_TOK*KTOT*CP];
static __device__ int   g_idx  [N_TOK*KTOT];
static __device__ float g_wbf  [NB*CP*NH];
static __device__ float g_b0   [NB*NH];

// bf16 activations
static __device__ bf16 g_sn_bf  [N_TOK*CS];
static __device__ bf16 g_S_bf   [N_TOK*CS];
static __device__ bf16 g_an_bf  [N_TOK*CT];
static __device__ bf16 g_otmp_bf[N_TOK*CT];
static __device__ bf16 g_hb_bf  [N_TOK*2*CT];

// bf16 pre-converted weights (adaLN sw/shw have sln_g folded in)
static __device__ bf16 g_w_a1sw [NB*CS*CT];
static __device__ bf16 g_w_a1shw[NB*CS*CT];
static __device__ bf16 g_w_q    [NB*CT*CT];
static __device__ bf16 g_w_k    [NB*CT*CT];
static __device__ bf16 g_w_v    [NB*CT*CT];
static __device__ bf16 g_w_g    [NB*CT*CT];
static __device__ bf16 g_w_o    [NB*CT*CT];
static __device__ bf16 g_w_sg   [NB*CS*CT];
static __device__ bf16 g_w_a2sw [NB*CS*CT];
static __device__ bf16 g_w_a2shw[NB*CS*CT];
static __device__ bf16 g_w_t1   [NB*CT*2*CT];
static __device__ bf16 g_w_t2   [NB*CT*2*CT];
static __device__ bf16 g_w_t3   [NB*2*CT*CT];
static __device__ bf16 g_w_tsg  [NB*CS*CT];

__device__ __forceinline__ float sigmoidf_(float x) { return 1.0f / (1.0f + expf(-x)); }

__device__ __forceinline__ unsigned sptr(const void* p) {
    return (unsigned)__cvta_generic_to_shared(p);
}

__device__ __forceinline__ void cpasync16(unsigned dst, const void* src) {
    asm volatile("cp.async.cg.shared.global [%0],[%1],16;" :: "r"(dst), "l"(src));
}
#define CP_COMMIT() asm volatile("cp.async.commit_group;")
template<int Nw>
__device__ __forceinline__ void cp_wait() {
    asm volatile("cp.async.wait_group %0;" :: "n"(Nw));
}

__device__ __forceinline__ void ldsm4(unsigned& r0, unsigned& r1, unsigned& r2, unsigned& r3,
                                      unsigned addr) {
    asm volatile("ldmatrix.sync.aligned.m8n8.x4.shared.b16 {%0,%1,%2,%3},[%4];"
                 : "=r"(r0), "=r"(r1), "=r"(r2), "=r"(r3) : "r"(addr));
}

__device__ __forceinline__ void ldsm4t(unsigned& r0, unsigned& r1, unsigned& r2, unsigned& r3,
                                       unsigned addr) {
    asm volatile("ldmatrix.sync.aligned.m8n8.x4.trans.shared.b16 {%0,%1,%2,%3},[%4];"
                 : "=r"(r0), "=r"(r1), "=r"(r2), "=r"(r3) : "r"(addr));
}

__device__ __forceinline__ void mma_bf16(float* c, const unsigned* a, unsigned b0, unsigned b1) {
    asm volatile(
        "mma.sync.aligned.m16n8k16.row.col.f32.bf16.bf16.f32 "
        "{%0,%1,%2,%3},{%4,%5,%6,%7},{%8,%9},{%0,%1,%2,%3};\n"
        : "+f"(c[0]), "+f"(c[1]), "+f"(c[2]), "+f"(c[3])
        : "r"(a[0]), "r"(a[1]), "r"(a[2]), "r"(a[3]), "r"(b0), "r"(b1));
}

// ---------------------------------------------------------------------------
// fp32 -> bf16 bulk convert; optional per-row gamma fold (row = idx/CT).
// ---------------------------------------------------------------------------
struct CvtEnt { const float* s; bf16* d; int n; const float* g; };
struct CvtList { CvtEnt e[15]; };

__global__ void cvt_kernel(CvtList L) {
    CvtEnt c = L.e[blockIdx.y];
    int stride = gridDim.x * blockDim.x;
    for (int i = blockIdx.x*blockDim.x + threadIdx.x; i*4 < c.n; i += stride) {
        float4 v = *(const float4*)(c.s + i*4);
        if (c.g) {
            float sc = c.g[(i*4)/CT];
            v.x *= sc; v.y *= sc; v.z *= sc; v.w *= sc;
        }
        *(bf162*)(c.d + i*4)     = __floats2bfloat162_rn(v.x, v.y);
        *(bf162*)(c.d + i*4 + 2) = __floats2bfloat162_rn(v.z, v.w);
    }
}

// ---------------------------------------------------------------------------
// kNN indices: warp-per-token iterative extract-min with (dist,idx) packed keys.
// ---------------------------------------------------------------------------
__global__ void idx_kernel(const float* __restrict__ X, int* __restrict__ idx) {
    __shared__ float xs0[N_TOK], xs1[N_TOK], xs2[N_TOK];
    int tid = threadIdx.x;
    for (int j = tid; j < N_TOK; j += 256) {
        xs0[j] = X[j*3+0]; xs1[j] = X[j*3+1]; xs2[j] = X[j*3+2];
    }
    __syncthreads();
    int lane = tid & 31, warp = tid >> 5;
    int n = blockIdx.x*8 + warp;
    if (lane < NLOC) {
        int v = n - NLOC/2 + lane;
        idx[n*KTOT + lane] = min(max(v, 0), N_TOK-1);
    }
    float x0 = xs0[n], x1 = xs1[n], x2 = xs2[n];

    unsigned removed = 0;
    unsigned long long bk = 0xFFFFFFFFFFFFFFFFull;
#pragma unroll
    for (int t = 0; t < 32; t++) {
        int j = lane + (t << 5);
        float d0 = x0 - xs0[j], d1 = x1 - xs1[j], d2 = x2 - xs2[j];
        float dd = d0*d0 + d1*d1 + d2*d2;
        unsigned long long k = ((unsigned long long)__float_as_uint(dd) << 32) | (unsigned)j;
        bk = min(bk, k);
    }
    for (int s = 0; s < NKNN; s++) {
        unsigned long long g = bk;
#pragma unroll
        for (int o = 16; o; o >>= 1) {
            unsigned long long other = __shfl_xor_sync(0xffffffffu, g, o);
            g = min(g, other);
        }
        int jstar = (int)(g & 0xffffffffu);
        if (lane == 0) idx[n*KTOT + NLOC + s] = jstar;
        if ((jstar & 31) == lane) {
            removed |= 1u << (jstar >> 5);
            bk = 0xFFFFFFFFFFFFFFFFull;
#pragma unroll
            for (int t = 0; t < 32; t++) {
                if (removed & (1u << t)) continue;
                int j = lane + (t << 5);
                float d0 = x0 - xs0[j], d1 = x1 - xs1[j], d2 = x2 - xs2[j];
                float dd = d0*d0 + d1*d1 + d2*d2;
                unsigned long long k = ((unsigned long long)__float_as_uint(dd) << 32) | (unsigned)j;
                bk = min(bk, k);
            }
        }
    }
}

// ---------------------------------------------------------------------------
// Gather pair reps + LayerNorm (affine folded into Wb later).
// ---------------------------------------------------------------------------
__global__ void zn_kernel(const float* __restrict__ Z, const int* __restrict__ idx,
                          float* __restrict__ zn) {
    int e = blockIdx.x * blockDim.x + threadIdx.x;
    if (e >= N_TOK*KTOT) return;
    int n = e / KTOT;
    int j = idx[e];
    const float* z = Z + ((size_t)n * N_TOK + j) * CP;
    float m = 0.f;
#pragma unroll
    for (int c = 0; c < CP; c++) m += z[c];
    m *= (1.0f/CP);
    float v = 0.f;
#pragma unroll
    for (int c = 0; c < CP; c++) { float d = z[c]-m; v += d*d; }
    v *= (1.0f/CP);
    float r = rsqrtf(v + 1e-5f);
#pragma unroll
    for (int c = 0; c < CP; c++) zn[(size_t)e*CP + c] = (z[c]-m)*r;
}

// ---------------------------------------------------------------------------
// Row LayerNorm; writes bf16 (if Ybf) or fp32 (Y). No gamma (folded upstream).
// ---------------------------------------------------------------------------
__global__ void ln_kernel(const float* __restrict__ X,
                          float* __restrict__ Y, bf16* __restrict__ Ybf, int W) {
    int n = blockIdx.x;
    int tid = threadIdx.x;
    const float* x = X + (size_t)n * W;
    int cnt = W >> 7;   // 3 or 6
    float v[6];
    float s = 0.f, s2 = 0.f;
    for (int i = 0; i < cnt; i++) {
        float t = x[tid + (i << 7)];
        v[i] = t; s += t; s2 += t*t;
    }
#pragma unroll
    for (int o = 16; o; o >>= 1) {
        s  += __shfl_xor_sync(0xffffffffu, s,  o);
        s2 += __shfl_xor_sync(0xffffffffu, s2, o);
    }
    __shared__ float ss[4], ss2[4];
    if ((tid & 31) == 0) { ss[tid >> 5] = s; ss2[tid >> 5] = s2; }
    __syncthreads();
    s  = ss[0]  + ss[1]  + ss[2]  + ss[3];
    s2 = ss2[0] + ss2[1] + ss2[2] + ss2[3];
    float m = s / W;
    float var = s2 / W - m*m;
    float r = rsqrtf(var + 1e-5f);
    for (int i = 0; i < cnt; i++) {
        int c = tid + (i << 7);
        float o = (v[i]-m)*r;
        if (Ybf) Ybf[(size_t)n*W + c] = __float2bfloat16(o);
        else     Y  [(size_t)n*W + c] = o;
    }
}

// ---------------------------------------------------------------------------
// Fold pair LN affine into Wb, all NB blocks in one launch.
// ---------------------------------------------------------------------------
__global__ void fold_wb_all(const float* __restrict__ plg, const float* __restrict__ plb,
                            const float* __restrict__ Wb,
                            float* __restrict__ wbf, float* __restrict__ b0) {
    int i = blockIdx.x;
    int t = threadIdx.x;
    const float* g  = plg + i*CP;
    const float* b  = plb + i*CP;
    const float* W  = Wb  + i*CP*NH;
    if (t < CP*NH) {
        int c = t / NH;
        wbf[i*CP*NH + t] = g[c] * W[t];
    }
    if (t < NH) {
        float s = 0.f;
#pragma unroll
        for (int c = 0; c < CP; c++) s += b[c] * W[c*NH + t];
        b0[i*NH + t] = s;
    }
}

// ---------------------------------------------------------------------------
// bf16 tensor-core GEMM core: 64x64x32 tiles, STAGES-deep cp.async pipeline,
// ldmatrix fragments, mma m16n8k16, fp32 accum. 8 warps (2x4), warp tile 32x16.
// Drains the pipeline (wait 0 + bar) before returning so smem can be reused.
// ---------------------------------------------------------------------------
#define BM 64
#define BN 64
#define BK 32
#define ASTRIDE 40   // 80B row stride, conflict-free ldmatrix
#define BSTRIDE 72   // 144B row stride, conflict-free ldmatrix

template<int STAGES, bool DUAL>
__device__ __forceinline__ void pipe_gemm(
        const bf16* __restrict__ A, const bf16* __restrict__ B1, const bf16* __restrict__ B2,
        int N, int K, int row0, int col0,
        unsigned short (*As)[BM][ASTRIDE], unsigned short (*Bs)[BK][BSTRIDE],
        unsigned short (*Bs2)[BK][BSTRIDE],
        float (&acc)[2][2][4], float (&acc2)[2][2][4]) {
    int tid = threadIdx.x;
    int lane = tid & 31, warp = tid >> 5;
    int wm = warp >> 2, wn = warp & 3;
    int arow = tid >> 2, ac = (tid & 3) << 3;
    int brow = tid >> 3, bc = (tid & 7) << 3;

    const bf16* Ag  = A  + (size_t)(row0 + arow)*K + ac;
    const bf16* B1g = B1 + (size_t)brow*N + col0 + bc;
    const bf16* B2g = DUAL ? (B2 + (size_t)brow*N + col0 + bc) : nullptr;

    auto issue = [&](int s, int k0) {
        cpasync16(sptr(&As[s][arow][ac]), Ag + k0);
        cpasync16(sptr(&Bs[s][brow][bc]), B1g + (size_t)k0*N);
        if (DUAL) cpasync16(sptr(&Bs2[s][brow][bc]), B2g + (size_t)k0*N);
    };

    int lm  = lane >> 3;
    int lr8 = lane & 7;
    int a_row_off = (lm & 1)*8 + lr8;
    int a_col_off = (lm >> 1)*8;
    int b_k_off   = (lm & 1)*8 + lr8;
    int b_n_off   = wn*16 + (lm >> 1)*8;

    int NIT = K / BK;                       // >= 12 for all shapes used
    constexpr int PREF = STAGES - 1;
#pragma unroll
    for (int p = 0; p < PREF; p++) { issue(p, p*BK); CP_COMMIT(); }

    for (int it = 0; it < NIT; it++) {
        cp_wait<STAGES-2>();
        __syncthreads();
        int s = it % STAGES;

#pragma unroll
        for (int ks = 0; ks < BK; ks += 16) {
            unsigned a[2][4], b[4], b2[4];
#pragma unroll
            for (int mi = 0; mi < 2; mi++) {
                int mr = wm*32 + mi*16;
                ldsm4(a[mi][0], a[mi][1], a[mi][2], a[mi][3],
                      sptr(&As[s][mr + a_row_off][ks + a_col_off]));
            }
            ldsm4t(b[0], b[1], b[2], b[3], sptr(&Bs[s][ks + b_k_off][b_n_off]));
            if (DUAL)
                ldsm4t(b2[0], b2[1], b2[2], b2[3], sptr(&Bs2[s][ks + b_k_off][b_n_off]));
#pragma unroll
            for (int mi = 0; mi < 2; mi++) {
                mma_bf16(acc[mi][0], a[mi], b[0], b[1]);
                mma_bf16(acc[mi][1], a[mi], b[2], b[3]);
                if (DUAL) {
                    mma_bf16(acc2[mi][0], a[mi], b2[0], b2[1]);
                    mma_bf16(acc2[mi][1], a[mi], b2[2], b2[3]);
                }
            }
        }

        if (it + PREF < NIT) issue((it + PREF) % STAGES, (it + PREF) * BK);
        CP_COMMIT();
    }
    cp_wait<0>();
    __syncthreads();
}

// MODE 0: C = acc1 + bias[c]       (bias nullable, fp32 out)
// MODE 1: C = sigmoid(acc1+bias)*extra + acc2   (adaLN dual, bf16 out)
// MODE 3: C = silu(acc1) * acc2                 (SwiGLU dual, bf16 out)
template<int MODE>
__global__ __launch_bounds__(256) void gemm_kernel(
        const bf16* __restrict__ A, const bf16* __restrict__ B1,
        const bf16* __restrict__ B2, const float* __restrict__ bias,
        const float* __restrict__ extra, void* __restrict__ Cp,
        int M, int N, int K) {
    constexpr bool DUAL = (MODE == 1 || MODE == 3);
    constexpr int STAGES = DUAL ? 3 : 5;
    __shared__ __align__(16) unsigned short As [STAGES][BM][ASTRIDE];
    __shared__ __align__(16) unsigned short Bs [STAGES][BK][BSTRIDE];
    __shared__ __align__(16) unsigned short Bs2[DUAL ? STAGES : 1][DUAL ? BK : 1][BSTRIDE];

    int row0 = blockIdx.y * BM, col0 = blockIdx.x * BN;
    float acc [2][2][4] = {};
    float acc2[2][2][4] = {};
    pipe_gemm<STAGES, DUAL>(A, B1, B2, N, K, row0, col0,
                            As, Bs, (unsigned short (*)[BK][BSTRIDE])Bs2, acc, acc2);

    int tid = threadIdx.x;
    int lane = tid & 31, warp = tid >> 5;
    int wm = warp >> 2, wn = warp & 3;
    int lr = lane >> 2, lc = lane & 3;
    float* Cf = (float*)Cp;
    bf16*  Cb = (bf16*)Cp;

#pragma unroll
    for (int mi = 0; mi < 2; mi++) {
#pragma unroll
        for (int half = 0; half < 2; half++) {
            int r = row0 + wm*32 + mi*16 + lr + half*8;
#pragma unroll
            for (int ni = 0; ni < 2; ni++) {
                int cidx = col0 + wn*16 + ni*8 + 2*lc;
                size_t off = (size_t)r*N + cidx;
                float v0 = acc[mi][ni][half*2+0];
                float v1 = acc[mi][ni][half*2+1];
                if (MODE == 0) {
                    float b0v = bias ? bias[cidx]   : 0.0f;
                    float b1v = bias ? bias[cidx+1] : 0.0f;
                    float2 out; out.x = v0 + b0v; out.y = v1 + b1v;
                    *(float2*)(Cf + off) = out;
                } else if (MODE == 1) {
                    float2 ex = *(const float2*)(extra + off);
                    float ox = sigmoidf_(v0 + bias[cidx  ]) * ex.x + acc2[mi][ni][half*2+0];
                    float oy = sigmoidf_(v1 + bias[cidx+1]) * ex.y + acc2[mi][ni][half*2+1];
                    *(bf162*)(Cb + off) = __floats2bfloat162_rn(ox, oy);
                } else { // MODE 3
                    float ox = v0 * sigmoidf_(v0) * acc2[mi][ni][half*2+0];
                    float oy = v1 * sigmoidf_(v1) * acc2[mi][ni][half*2+1];
                    *(bf162*)(Cb + off) = __floats2bfloat162_rn(ox, oy);
                }
            }
        }
    }
}

// Fused skip-gate: C += sigmoid(A2@W2 + bias) * (A1@W1). Two sequential
// pipelined accumulations sharing smem; single RMW epilogue on fp32 C.
__global__ __launch_bounds__(256) void gemm_fused_kernel(
        const bf16* __restrict__ A1, const bf16* __restrict__ W1, int K1,
        const bf16* __restrict__ A2, const bf16* __restrict__ W2, int K2,
        const float* __restrict__ bias, float* __restrict__ C, int N) {
    constexpr int STAGES = 5;
    __shared__ __align__(16) unsigned short As[STAGES][BM][ASTRIDE];
    __shared__ __align__(16) unsigned short Bs[STAGES][BK][BSTRIDE];

    int row0 = blockIdx.y * BM, col0 = blockIdx.x * BN;
    float acc1[2][2][4] = {};
    float acc2[2][2][4] = {};
    float dummy[2][2][4];
    pipe_gemm<STAGES, false>(A1, W1, nullptr, N, K1, row0, col0, As, Bs, nullptr, acc1, dummy);
    pipe_gemm<STAGES, false>(A2, W2, nullptr, N, K2, row0, col0, As, Bs, nullptr, acc2, dummy);

    int tid = threadIdx.x;
    int lane = tid & 31, warp = tid >> 5;
    int wm = warp >> 2, wn = warp & 3;
    int lr = lane >> 2, lc = lane & 3;

#pragma unroll
    for (int mi = 0; mi < 2; mi++) {
#pragma unroll
        for (int half = 0; half < 2; half++) {
            int r = row0 + wm*32 + mi*16 + lr + half*8;
#pragma unroll
            for (int ni = 0; ni < 2; ni++) {
                int cidx = col0 + wn*16 + ni*8 + 2*lc;
                size_t off = (size_t)r*N + cidx;
                float2 cv = *(const float2*)(C + off);
                cv.x += sigmoidf_(acc2[mi][ni][half*2+0] + bias[cidx  ]) * acc1[mi][ni][half*2+0];
                cv.y += sigmoidf_(acc2[mi][ni][half*2+1] + bias[cidx+1]) * acc1[mi][ni][half*2+1];
                *(float2*)(C + off) = cv;
            }
        }
    }
}

// 4 MODE-0 GEMMs (same A) in one launch, selected by blockIdx.z.
struct QuadParams {
    const bf16* B[4];
    const float* bias[4];
    float* C[4];
};

__global__ __launch_bounds__(256) void gemm_quad_kernel(
        const bf16* __restrict__ A, QuadParams p, int M, int N, int K) {
    constexpr int STAGES = 5;
    __shared__ __align__(16) unsigned short As[STAGES][BM][ASTRIDE];
    __shared__ __align__(16) unsigned short Bs[STAGES][BK][BSTRIDE];
    int z = blockIdx.z;
    int row0 = blockIdx.y * BM, col0 = blockIdx.x * BN;
    float acc[2][2][4] = {};
    float dummy[2][2][4];
    pipe_gemm<STAGES, false>(A, p.B[z], nullptr, N, K, row0, col0, As, Bs, nullptr, acc, dummy);

    int tid = threadIdx.x;
    int lane = tid & 31, warp = tid >> 5;
    int wm = warp >> 2, wn = warp & 3;
    int lr = lane >> 2, lc = lane & 3;
    const float* bias = p.bias[z];
    float* Cf = p.C[z];

#pragma unroll
    for (int mi = 0; mi < 2; mi++) {
#pragma unroll
        for (int half = 0; half < 2; half++) {
            int r = row0 + wm*32 + mi*16 + lr + half*8;
#pragma unroll
            for (int ni = 0; ni < 2; ni++) {
                int cidx = col0 + wn*16 + ni*8 + 2*lc;
                size_t off = (size_t)r*N + cidx;
                float b0v = bias ? bias[cidx]   : 0.0f;
                float b1v = bias ? bias[cidx+1] : 0.0f;
                float2 out;
                out.x = acc[mi][ni][half*2+0] + b0v;
                out.y = acc[mi][ni][half*2+1] + b1v;
                *(float2*)(Cf + off) = out;
            }
        }
    }
}

// ---------------------------------------------------------------------------
// Attention: per-token block. 16 heads x 40 keys, pair bias, softmax,
// weighted V sum, per-channel sigmoid gate (gpre). Writes bf16.
// ---------------------------------------------------------------------------
__global__ void attn_kernel(const float* __restrict__ q, const float* __restrict__ kb,
                            const float* __restrict__ vb, const float* __restrict__ gpre,
                            const int* __restrict__ idx, const float* __restrict__ zn,
                            const float* __restrict__ wbf, const float* __restrict__ b0,
                            bf16* __restrict__ out) {
    const float SCALE = 0.14433756729740643f; // 1/sqrt(48)
    int n = blockIdx.x;
    int tid = threadIdx.x;
    __shared__ float qs[CT];
    __shared__ float zs[KTOT*CP];
    __shared__ int   js[KTOT];
    __shared__ float sc[NH*KTOT];

    for (int c = tid; c < CT; c += 256) qs[c] = q[(size_t)n*CT + c];
    if (tid < KTOT) js[tid] = idx[n*KTOT + tid];
    for (int c = tid; c < KTOT*CP; c += 256) zs[c] = zn[(size_t)n*KTOT*CP + c];
    __syncthreads();

    for (int e = tid; e < NH*KTOT; e += 256) {
        int h = e / KTOT, k = e % KTOT;
        int j = js[k];
        const float* kp = kb + (size_t)j*CT + h*DH;
        const float* qp = qs + h*DH;
        float s = 0.f;
#pragma unroll
        for (int d = 0; d < DH; d++) s += qp[d]*kp[d];
        s *= SCALE;
        float bb = b0[h];
        const float* zp = zs + k*CP;
#pragma unroll
        for (int c = 0; c < CP; c++) bb += zp[c]*wbf[c*NH + h];
        sc[e] = s + bb;
    }
    __syncthreads();

    if (tid < NH) {
        int h = tid;
        float mx = -FLT_MAX;
        for (int k = 0; k < KTOT; k++) mx = fmaxf(mx, sc[h*KTOT + k]);
        float sum = 0.f;
        for (int k = 0; k < KTOT; k++) {
            float ex = expf(sc[h*KTOT + k] - mx);
            sc[h*KTOT + k] = ex; sum += ex;
        }
        float inv = 1.0f / sum;
        for (int k = 0; k < KTOT; k++) sc[h*KTOT + k] *= inv;
    }
    __syncthreads();

    for (int c = tid; c < CT; c += 256) {
        int h = c / DH;
        float acc = 0.f;
#pragma unroll 8
        for (int k = 0; k < KTOT; k++)
            acc += sc[h*KTOT + k] * vb[(size_t)js[k]*CT + c];
        float g = gpre[(size_t)n*CT + c];
        out[(size_t)n*CT + c] = __float2bfloat16(acc * sigmoidf_(g));
    }
}

// ---------------------------------------------------------------------------
extern "C" void kernel_launch(void* const* d_in, const int* in_sizes, int n_in,
                              void* d_out, int out_size) {
    const float* A_I      = (const float*)d_in[0];
    const float* S        = (const float*)d_in[1];
    const float* Z        = (const float*)d_in[2];
    const float* X_L      = (const float*)d_in[3];
    const float* aln1_g   = (const float*)d_in[5];
    const float* aln1_sw  = (const float*)d_in[6];
    const float* aln1_sb  = (const float*)d_in[7];
    const float* aln1_shw = (const float*)d_in[8];
    const float* Wq       = (const float*)d_in[9];
    const float* bq       = (const float*)d_in[10];
    const float* Wk       = (const float*)d_in[11];
    const float* Wv       = (const float*)d_in[12];
    const float* plg      = (const float*)d_in[13];
    const float* plb      = (const float*)d_in[14];
    const float* Wb       = (const float*)d_in[15];
    const float* Wg       = (const float*)d_in[16];
    const float* Wo       = (const float*)d_in[17];
    const float* sgw      = (const float*)d_in[18];
    const float* sgb      = (const float*)d_in[19];
    const float* aln2_g   = (const float*)d_in[20];
    const float* aln2_sw  = (const float*)d_in[21];
    const float* aln2_sb  = (const float*)d_in[22];
    const float* aln2_shw = (const float*)d_in[23];
    const float* tw1      = (const float*)d_in[24];
    const float* tw2      = (const float*)d_in[25];
    const float* tw3      = (const float*)d_in[26];
    const float* tsgw     = (const float*)d_in[27];
    const float* tsgb     = (const float*)d_in[28];

    float* A = (float*)d_out;

    float *normA, *q, *kb, *vb, *gpre, *zn, *wbf, *b0;
    int* idx;
    bf16 *sn_bf, *S_bf, *an_bf, *otmp_bf, *hb_bf;
    bf16 *w_a1sw, *w_a1shw, *w_q, *w_k, *w_v, *w_g, *w_o, *w_sg;
    bf16 *w_a2sw, *w_a2shw, *w_t1, *w_t2, *w_t3, *w_tsg;

    cudaGetSymbolAddress((void**)&normA,   g_normA);
    cudaGetSymbolAddress((void**)&q,       g_q);
    cudaGetSymbolAddress((void**)&kb,      g_kb);
    cudaGetSymbolAddress((void**)&vb,      g_vb);
    cudaGetSymbolAddress((void**)&gpre,    g_gpre);
    cudaGetSymbolAddress((void**)&zn,      g_zn);
    cudaGetSymbolAddress((void**)&wbf,     g_wbf);
    cudaGetSymbolAddress((void**)&b0,      g_b0);
    cudaGetSymbolAddress((void**)&idx,     g_idx);
    cudaGetSymbolAddress((void**)&sn_bf,   g_sn_bf);
    cudaGetSymbolAddress((void**)&S_bf,    g_S_bf);
    cudaGetSymbolAddress((void**)&an_bf,   g_an_bf);
    cudaGetSymbolAddress((void**)&otmp_bf, g_otmp_bf);
    cudaGetSymbolAddress((void**)&hb_bf,   g_hb_bf);
    cudaGetSymbolAddress((void**)&w_a1sw,  g_w_a1sw);
    cudaGetSymbolAddress((void**)&w_a1shw, g_w_a1shw);
    cudaGetSymbolAddress((void**)&w_q,     g_w_q);
    cudaGetSymbolAddress((void**)&w_k,     g_w_k);
    cudaGetSymbolAddress((void**)&w_v,     g_w_v);
    cudaGetSymbolAddress((void**)&w_g,     g_w_g);
    cudaGetSymbolAddress((void**)&w_o,     g_w_o);
    cudaGetSymbolAddress((void**)&w_sg,    g_w_sg);
    cudaGetSymbolAddress((void**)&w_a2sw,  g_w_a2sw);
    cudaGetSymbolAddress((void**)&w_a2shw, g_w_a2shw);
    cudaGetSymbolAddress((void**)&w_t1,    g_w_t1);
    cudaGetSymbolAddress((void**)&w_t2,    g_w_t2);
    cudaGetSymbolAddress((void**)&w_t3,    g_w_t3);
    cudaGetSymbolAddress((void**)&w_tsg,   g_w_tsg);

    cudaMemcpyAsync(A, A_I, (size_t)N_TOK*CT*sizeof(float), cudaMemcpyDeviceToDevice, 0);

    // One-shot conversions: weights (adaLN sw/shw get sln_g folded) + S
    CvtList cl;
    cl.e[0]  = { aln1_sw,  w_a1sw,  NB*CS*CT,   aln1_g };
    cl.e[1]  = { aln1_shw, w_a1shw, NB*CS*CT,   aln1_g };
    cl.e[2]  = { Wq,       w_q,     NB*CT*CT,   nullptr };
    cl.e[3]  = { Wk,       w_k,     NB*CT*CT,   nullptr };
    cl.e[4]  = { Wv,       w_v,     NB*CT*CT,   nullptr };
    cl.e[5]  = { Wg,       w_g,     NB*CT*CT,   nullptr };
    cl.e[6]  = { Wo,       w_o,     NB*CT*CT,   nullptr };
    cl.e[7]  = { sgw,      w_sg,    NB*CS*CT,   nullptr };
    cl.e[8]  = { aln2_sw,  w_a2sw,  NB*CS*CT,   aln2_g };
    cl.e[9]  = { aln2_shw, w_a2shw, NB*CS*CT,   aln2_g };
    cl.e[10] = { tw1,      w_t1,    NB*CT*2*CT, nullptr };
    cl.e[11] = { tw2,      w_t2,    NB*CT*2*CT, nullptr };
    cl.e[12] = { tw3,      w_t3,    NB*2*CT*CT, nullptr };
    cl.e[13] = { tsgw,     w_tsg,   NB*CS*CT,   nullptr };
    cl.e[14] = { S,        S_bf,    N_TOK*CS,   nullptr };
    cvt_kernel<<<dim3(128, 15), 256>>>(cl);

    idx_kernel<<<N_TOK/8, 256>>>(X_L, idx);
    zn_kernel<<<(N_TOK*KTOT + 255)/256, 256>>>(Z, idx, zn);
    fold_wb_all<<<NB, 256>>>(plg, plb, Wb, wbf, b0);
    ln_kernel<<<N_TOK, 128>>>(S, nullptr, sn_bf, CS);   // ln(S) once (gamma folded)

    dim3 g768(CT/BN, N_TOK/BM);
    dim3 g1536(2*CT/BN, N_TOK/BM);
    dim3 gq(CT/BN, N_TOK/BM, 4);

    for (int i = 0; i < NB; i++) {
        size_t wo_ct  = (size_t)i*CT*CT;
        size_t wo_cs  = (size_t)i*CS*CT;
        size_t wo_t12 = (size_t)i*CT*2*CT;
        size_t wo_t3  = (size_t)i*2*CT*CT;

        // --- LocalAttentionPairBias ---
        ln_kernel<<<N_TOK, 128>>>(A, normA, nullptr, CT);
        gemm_kernel<1><<<g768, 256>>>(sn_bf, w_a1sw + wo_cs, w_a1shw + wo_cs,
                                      aln1_sb + i*CT, normA, an_bf, N_TOK, CT, CS);
        QuadParams qp;
        qp.B[0] = w_q + wo_ct; qp.bias[0] = bq + i*CT; qp.C[0] = q;
        qp.B[1] = w_k + wo_ct; qp.bias[1] = nullptr;   qp.C[1] = kb;
        qp.B[2] = w_v + wo_ct; qp.bias[2] = nullptr;   qp.C[2] = vb;
        qp.B[3] = w_g + wo_ct; qp.bias[3] = nullptr;   qp.C[3] = gpre;
        gemm_quad_kernel<<<gq, 256>>>(an_bf, qp, N_TOK, CT, CT);
        attn_kernel<<<N_TOK, 256>>>(q, kb, vb, gpre, idx, zn,
                                    wbf + i*CP*NH, b0 + i*NH, otmp_bf);
        gemm_fused_kernel<<<g768, 256>>>(otmp_bf, w_o + wo_ct, CT,
                                         S_bf, w_sg + wo_cs, CS,
                                         sgb + i*CT, A, CT);

        // --- ConditionedTransitionBlock ---
        ln_kernel<<<N_TOK, 128>>>(A, normA, nullptr, CT);
        gemm_kernel<1><<<g768, 256>>>(sn_bf, w_a2sw + wo_cs, w_a2shw + wo_cs,
                                      aln2_sb + i*CT, normA, an_bf, N_TOK, CT, CS);
        gemm_kernel<3><<<g1536, 256>>>(an_bf, w_t1 + wo_t12, w_t2 + wo_t12, nullptr, nullptr,
                                       hb_bf, N_TOK, 2*CT, CT);
        gemm_fused_kernel<<<g768, 256>>>(hb_bf, w_t3 + wo_t3, 2*CT,
                                         S_bf, w_tsg + wo_cs, CS,
                                         tsgb + i*CT, A, CT);
    }
}